// round 2
// baseline (speedup 1.0000x reference)
#include <cuda_runtime.h>
#include <cuda_bf16.h>
#include <cstdio>

// ---------------- problem constants ----------------
#define BATCH 64
#define RES 28
#define RES2 14
#define NH 8
#define KD 16
#define DV 64
#define DH 512
#define CIN 384
#define COUT 768
#define NKEY (RES*RES)      // 784
#define NQ (RES2*RES2)      // 196
#define MQ (BATCH*NQ)       // 12544
#define MK (BATCH*NKEY)     // 50176

// ---------------- device scratch ----------------
__device__ float g_qds[(size_t)MQ * CIN];      // 12544 x 384
__device__ float g_q  [(size_t)MQ * (NH*KD)];  // 12544 x 128
__device__ float g_k  [(size_t)MK * (NH*KD)];  // 50176 x 128
__device__ float g_v  [(size_t)MK * DH];       // 50176 x 512
__device__ float g_vloc[(size_t)MQ * DH];      // 12544 x 512
__device__ float g_ao [(size_t)MQ * DH];       // 12544 x 512

// ---------------- depthwise 3x3 stride-2 SAME conv + residual subsample (for q) ----
__global__ void conv_q_kernel(const float* __restrict__ x,
                              const float* __restrict__ w,
                              const float* __restrict__ bias) {
    int idx = blockIdx.x * blockDim.x + threadIdx.x;
    const int total = BATCH * NQ * CIN;
    if (idx >= total) return;
    int c  = idx % CIN;
    int p  = idx / CIN;
    int b  = p / NQ;
    int pp = p % NQ;
    int oy = pp / RES2, ox = pp % RES2;
    float acc = bias[c];
#pragma unroll
    for (int dy = 0; dy < 3; dy++) {
        int iy = 2*oy + dy;
        if (iy >= RES) continue;
#pragma unroll
        for (int dx = 0; dx < 3; dx++) {
            int ix = 2*ox + dx;
            if (ix >= RES) continue;
            acc += x[(((size_t)b*RES + iy)*RES + ix)*CIN + c] * w[(dy*3+dx)*CIN + c];
        }
    }
    // + x[:, ::2, ::2, :]
    acc += x[(((size_t)b*RES + 2*oy)*RES + 2*ox)*CIN + c];
    g_qds[idx] = acc;
}

// ---------------- depthwise 3x3 stride-2 SAME conv + BN (for v_local) ----------
__global__ void conv_vloc_kernel(const float* __restrict__ w,
                                 const float* __restrict__ bias,
                                 const float* __restrict__ bns,
                                 const float* __restrict__ bnb) {
    int idx = blockIdx.x * blockDim.x + threadIdx.x;
    const int total = BATCH * NQ * DH;
    if (idx >= total) return;
    int c  = idx % DH;
    int p  = idx / DH;
    int b  = p / NQ;
    int pp = p % NQ;
    int oy = pp / RES2, ox = pp % RES2;
    float acc = bias[c];
#pragma unroll
    for (int dy = 0; dy < 3; dy++) {
        int iy = 2*oy + dy;
        if (iy >= RES) continue;
#pragma unroll
        for (int dx = 0; dx < 3; dx++) {
            int ix = 2*ox + dx;
            if (ix >= RES) continue;
            acc += g_v[(((size_t)b*RES + iy)*RES + ix)*DH + c] * w[(dy*3+dx)*DH + c];
        }
    }
    g_vloc[idx] = acc * bns[c] + bnb[c];
}

// ---------------- generic tiled fp32 GEMM + fused (bias)*s + b epilogue ----------
// Y[m,n] = (sum_k A[m,k]*W[k,n] + bias[n]) * s[n] + b2[n]
// requires M%64==0, N%64==0, K%16==0 (true for all call sites)
#define BM 64
#define BN 64
#define BKK 16
__global__ void __launch_bounds__(256, 4)
gemm_bn_kernel(const float* __restrict__ A, const float* __restrict__ W,
               const float* __restrict__ bias, const float* __restrict__ bns,
               const float* __restrict__ bnb, float* __restrict__ Y,
               int M, int N, int K) {
    __shared__ float As[BKK][BM + 1];
    __shared__ float Bs[BKK][BN];
    const int bm = blockIdx.y * BM, bn = blockIdx.x * BN;
    const int tid = threadIdx.x;
    const int tx = tid % 16, ty = tid / 16;
    float acc[4][4] = {};
    for (int k0 = 0; k0 < K; k0 += BKK) {
        for (int i = tid; i < BM*BKK; i += 256) {
            int r = i / BKK, c = i % BKK;
            As[c][r] = A[(size_t)(bm + r) * K + k0 + c];
        }
        for (int i = tid; i < BKK*BN; i += 256) {
            int r = i / BN, c = i % BN;
            Bs[r][c] = W[(size_t)(k0 + r) * N + bn + c];
        }
        __syncthreads();
#pragma unroll
        for (int kk = 0; kk < BKK; kk++) {
            float a[4], b[4];
#pragma unroll
            for (int i = 0; i < 4; i++) a[i] = As[kk][ty*4 + i];
#pragma unroll
            for (int j = 0; j < 4; j++) b[j] = Bs[kk][tx*4 + j];
#pragma unroll
            for (int i = 0; i < 4; i++)
#pragma unroll
                for (int j = 0; j < 4; j++)
                    acc[i][j] += a[i] * b[j];
        }
        __syncthreads();
    }
#pragma unroll
    for (int i = 0; i < 4; i++) {
        int row = bm + ty*4 + i;
#pragma unroll
        for (int j = 0; j < 4; j++) {
            int col = bn + tx*4 + j;
            Y[(size_t)row * N + col] = (acc[i][j] + bias[col]) * bns[col] + bnb[col];
        }
    }
}

// ---------------- fused attention ----------------
// grid: (7, 8, 64)  block: 256
// block handles 28 query rows of one (batch, head): scores + bias, softmax, P@V, +v_local
#define QT 28
#define SPITCH 788          // 784 + 4 pad
#define KTILE 56
__global__ void __launch_bounds__(256)
attn_kernel(const float* __restrict__ attn_bias) {
    const int qt = blockIdx.x, h = blockIdx.y, b = blockIdx.z;
    extern __shared__ float sm[];
    float* sQ    = sm;                       // QT*16        = 448
    float* sS    = sQ + QT*16;               // QT*SPITCH    = 22064
    float* sV    = sS + QT*SPITCH;           // KTILE*64     = 3584
    float* sInv  = sV + KTILE*64;            // QT           = 28
    float* sBias = sInv + QT;                // NKEY         = 784
    const int tid = threadIdx.x;
    const int q0 = qt * QT;

    // stage Q rows + this head's bias table
    for (int i = tid; i < QT*KD; i += 256) {
        int q = i / KD, t = i % KD;
        sQ[i] = g_q[((size_t)(b*NQ) + q0 + q) * (NH*KD) + h*KD + t];
    }
    for (int i = tid; i < NKEY; i += 256) sBias[i] = attn_bias[h*NKEY + i];
    __syncthreads();

    // phase 1: S[q][j] = 0.25 * q·k + bias
    for (int j = tid; j < NKEY; j += 256) {
        float kr[KD];
        const float* kp = g_k + ((size_t)(b*NKEY) + j) * (NH*KD) + h*KD;
#pragma unroll
        for (int t = 0; t < KD; t++) kr[t] = kp[t];
        const int jx = j % RES, jy = j / RES;
#pragma unroll 4
        for (int q = 0; q < QT; q++) {
            const int qg = q0 + q;
            const int qx = 2*(qg % RES2), qy = 2*(qg / RES2);
            float s = 0.f;
#pragma unroll
            for (int t = 0; t < KD; t++) s += sQ[q*KD + t] * kr[t];
            const int dxa = qx > jx ? qx - jx : jx - qx;
            const int dya = qy > jy ? qy - jy : jy - qy;
            sS[q*SPITCH + j] = s * 0.25f + sBias[dxa*RES + dya];
        }
    }
    __syncthreads();

    // phase 2: row softmax (store unnormalized exp, keep 1/sum)
    const int warp = tid >> 5, lane = tid & 31;
    for (int r = warp; r < QT; r += 8) {
        float m = -1e30f;
        for (int j = lane; j < NKEY; j += 32) m = fmaxf(m, sS[r*SPITCH + j]);
#pragma unroll
        for (int o = 16; o > 0; o >>= 1) m = fmaxf(m, __shfl_xor_sync(0xffffffffu, m, o));
        float sum = 0.f;
        for (int j = lane; j < NKEY; j += 32) {
            float e = __expf(sS[r*SPITCH + j] - m);
            sS[r*SPITCH + j] = e;
            sum += e;
        }
#pragma unroll
        for (int o = 16; o > 0; o >>= 1) sum += __shfl_xor_sync(0xffffffffu, sum, o);
        if (lane == 0) sInv[r] = 1.f / sum;
    }
    __syncthreads();

    // phase 3: O = P @ V (V staged in smem tiles), + v_local, normalize
    const int d = tid & 63, qg4 = tid >> 6;       // 4 query-groups of 7
    float acc[7] = {};
    for (int kt = 0; kt < NKEY; kt += KTILE) {
        for (int i = tid; i < KTILE*64; i += 256) {
            int j = i >> 6, dd = i & 63;
            sV[i] = g_v[((size_t)(b*NKEY) + kt + j) * DH + h*DV + dd];
        }
        __syncthreads();
#pragma unroll
        for (int t = 0; t < 7; t++) {
            const int q = qg4*7 + t;
            float a = 0.f;
#pragma unroll 8
            for (int j = 0; j < KTILE; j++) a += sS[q*SPITCH + kt + j] * sV[j*64 + d];
            acc[t] += a;
        }
        __syncthreads();
    }
#pragma unroll
    for (int t = 0; t < 7; t++) {
        const int q = qg4*7 + t;
        const size_t o = ((size_t)(b*NQ) + q0 + q) * DH + h*DV + d;
        g_ao[o] = acc[t] * sInv[q] + g_vloc[o];
    }
}

// ---------------- launch ----------------
extern "C" void kernel_launch(void* const* d_in, const int* in_sizes, int n_in,
                              void* d_out, int out_size) {
    const float* x         = (const float*)d_in[0];
    const float* q_local_w = (const float*)d_in[1];
    const float* q_local_b = (const float*)d_in[2];
    const float* q_proj_w  = (const float*)d_in[3];
    const float* q_proj_b  = (const float*)d_in[4];
    const float* q_bn_s    = (const float*)d_in[5];
    const float* q_bn_b    = (const float*)d_in[6];
    const float* k_w       = (const float*)d_in[7];
    const float* k_b       = (const float*)d_in[8];
    const float* k_bn_s    = (const float*)d_in[9];
    const float* k_bn_b    = (const float*)d_in[10];
    const float* v_w       = (const float*)d_in[11];
    const float* v_b       = (const float*)d_in[12];
    const float* v_bn_s    = (const float*)d_in[13];
    const float* v_bn_b    = (const float*)d_in[14];
    const float* vloc_w    = (const float*)d_in[15];
    const float* vloc_b    = (const float*)d_in[16];
    const float* vloc_bn_s = (const float*)d_in[17];
    const float* vloc_bn_b = (const float*)d_in[18];
    const float* proj_w    = (const float*)d_in[19];
    const float* proj_b    = (const float*)d_in[20];
    const float* proj_bn_s = (const float*)d_in[21];
    const float* proj_bn_b = (const float*)d_in[22];
    const float* attn_bias = (const float*)d_in[23];
    float* out = (float*)d_out;

    float *p_qds, *p_q, *p_k, *p_v, *p_ao;
    cudaGetSymbolAddress((void**)&p_qds, g_qds);
    cudaGetSymbolAddress((void**)&p_q,   g_q);
    cudaGetSymbolAddress((void**)&p_k,   g_k);
    cudaGetSymbolAddress((void**)&p_v,   g_v);
    cudaGetSymbolAddress((void**)&p_ao,  g_ao);

    // 1. q local conv + subsample residual -> g_qds [12544, 384]
    {
        int total = BATCH * NQ * CIN;
        conv_q_kernel<<<(total + 255)/256, 256>>>(x, q_local_w, q_local_b);
    }
    // 2. q projection: g_qds @ q_proj_w -> g_q [12544, 128]
    {
        dim3 grid((NH*KD)/BN, MQ/BM);
        gemm_bn_kernel<<<grid, 256>>>(p_qds, q_proj_w, q_proj_b, q_bn_s, q_bn_b, p_q,
                                      MQ, NH*KD, CIN);
    }
    // 3. k: x @ k_w -> g_k [50176, 128]
    {
        dim3 grid((NH*KD)/BN, MK/BM);
        gemm_bn_kernel<<<grid, 256>>>(x, k_w, k_b, k_bn_s, k_bn_b, p_k,
                                      MK, NH*KD, CIN);
    }
    // 4. v: x @ v_w -> g_v [50176, 512]
    {
        dim3 grid(DH/BN, MK/BM);
        gemm_bn_kernel<<<grid, 256>>>(x, v_w, v_b, v_bn_s, v_bn_b, p_v,
                                      MK, DH, CIN);
    }
    // 5. v_local conv -> g_vloc [12544, 512]
    {
        int total = BATCH * NQ * DH;
        conv_vloc_kernel<<<(total + 255)/256, 256>>>(vloc_w, vloc_b, vloc_bn_s, vloc_bn_b);
    }
    // 6. attention (+v_local) -> g_ao [12544, 512]
    {
        const int smem = (QT*KD + QT*SPITCH + KTILE*64 + QT + NKEY) * sizeof(float);
        cudaFuncSetAttribute(attn_kernel, cudaFuncAttributeMaxDynamicSharedMemorySize, smem);
        dim3 grid(NQ/QT, NH, BATCH);
        attn_kernel<<<grid, 256, smem>>>(attn_bias);
    }
    // 7. projection: g_ao @ proj_w -> out [12544, 768]
    {
        dim3 grid(COUT/BN, MQ/BM);
        gemm_bn_kernel<<<grid, 256>>>(p_ao, proj_w, proj_b, proj_bn_s, proj_bn_b, out,
                                      MQ, COUT, DH);
    }
}

// round 3
// speedup vs baseline: 1.6401x; 1.6401x over previous
#include <cuda_runtime.h>
#include <cuda_bf16.h>
#include <cstdint>

// ---------------- problem constants ----------------
#define BATCH 64
#define RES 28
#define RES2 14
#define NH 8
#define KD 16
#define DV 64
#define DH 512
#define CIN 384
#define COUT 768
#define NKEY (RES*RES)      // 784
#define NQ (RES2*RES2)      // 196
#define MQ (BATCH*NQ)       // 12544
#define MK (BATCH*NKEY)     // 50176

// ---------------- device scratch ----------------
__device__ float g_qds[(size_t)MQ * CIN];      // 12544 x 384
__device__ float g_q  [(size_t)MQ * (NH*KD)];  // 12544 x 128
__device__ float g_k  [(size_t)MK * (NH*KD)];  // 50176 x 128
__device__ float g_v  [(size_t)MK * DH];       // 50176 x 512
__device__ float g_vloc[(size_t)MQ * DH];      // 12544 x 512
__device__ float g_ao [(size_t)MQ * DH];       // 12544 x 512

// ---------------- depthwise 3x3 stride-2 SAME conv + residual subsample (for q) ----
__global__ void conv_q_kernel(const float* __restrict__ x,
                              const float* __restrict__ w,
                              const float* __restrict__ bias) {
    int idx = blockIdx.x * blockDim.x + threadIdx.x;
    const int total = BATCH * NQ * CIN;
    if (idx >= total) return;
    int c  = idx % CIN;
    int p  = idx / CIN;
    int b  = p / NQ;
    int pp = p % NQ;
    int oy = pp / RES2, ox = pp % RES2;
    float acc = bias[c];
#pragma unroll
    for (int dy = 0; dy < 3; dy++) {
        int iy = 2*oy + dy;
        if (iy >= RES) continue;
#pragma unroll
        for (int dx = 0; dx < 3; dx++) {
            int ix = 2*ox + dx;
            if (ix >= RES) continue;
            acc += x[(((size_t)b*RES + iy)*RES + ix)*CIN + c] * w[(dy*3+dx)*CIN + c];
        }
    }
    acc += x[(((size_t)b*RES + 2*oy)*RES + 2*ox)*CIN + c];
    g_qds[idx] = acc;
}

// ---------------- depthwise 3x3 stride-2 SAME conv + BN (for v_local) ----------
__global__ void conv_vloc_kernel(const float* __restrict__ w,
                                 const float* __restrict__ bias,
                                 const float* __restrict__ bns,
                                 const float* __restrict__ bnb) {
    int idx = blockIdx.x * blockDim.x + threadIdx.x;
    const int total = BATCH * NQ * DH;
    if (idx >= total) return;
    int c  = idx % DH;
    int p  = idx / DH;
    int b  = p / NQ;
    int pp = p % NQ;
    int oy = pp / RES2, ox = pp % RES2;
    float acc = bias[c];
#pragma unroll
    for (int dy = 0; dy < 3; dy++) {
        int iy = 2*oy + dy;
        if (iy >= RES) continue;
#pragma unroll
        for (int dx = 0; dx < 3; dx++) {
            int ix = 2*ox + dx;
            if (ix >= RES) continue;
            acc += g_v[(((size_t)b*RES + iy)*RES + ix)*DH + c] * w[(dy*3+dx)*DH + c];
        }
    }
    g_vloc[idx] = acc * bns[c] + bnb[c];
}

// ---------------- tf32 tensor-core GEMM + fused (bias)*s + b epilogue ----------
// Y[m,n] = (sum_k A[m,k]*W[k,n] + bias[n]) * s[n] + b2[n]
// requires M%128==0, N%128==0, K%16==0 (true for all call sites)
#define GBM 128
#define GBN 128
#define GBK 16
#define PITCH 136   // %4==0 (float4 stores), tid4-stride banks {0,8,16,24}

__device__ __forceinline__ uint32_t f2tf32(float f) {
    uint32_t r;
    asm("cvt.rna.tf32.f32 %0, %1;\n" : "=r"(r) : "f"(f));
    return r;
}

__global__ void __launch_bounds__(256)
gemm_tf32_kernel(const float* __restrict__ A, const float* __restrict__ W,
                 const float* __restrict__ bias, const float* __restrict__ bns,
                 const float* __restrict__ bnb, float* __restrict__ Y,
                 int M, int N, int K) {
    __shared__ float As[GBK * PITCH];   // [k][m], pitch 136
    __shared__ float Bs[GBK * PITCH];   // [k][n], pitch 136
    const int bm = blockIdx.y * GBM, bn = blockIdx.x * GBN;
    const int tid = threadIdx.x;
    const int warp = tid >> 5, lane = tid & 31;
    const int grp = lane >> 2, t4 = lane & 3;
    const int wm = (warp & 3) * 32;     // warp row offset (4 warps along M)
    const int wn = (warp >> 2) * 64;    // warp col offset (2 warps along N)

    float acc[2][8][4];
#pragma unroll
    for (int i = 0; i < 2; i++)
#pragma unroll
        for (int j = 0; j < 8; j++)
#pragma unroll
            for (int c = 0; c < 4; c++) acc[i][j][c] = 0.f;

    for (int k0 = 0; k0 < K; k0 += GBK) {
        // stage A tile (128 x 16), transposed into As[k][m]
#pragma unroll
        for (int it = 0; it < 2; it++) {
            int i = tid + it * 256;
            int r = i >> 2, c4 = i & 3;
            float4 v = *reinterpret_cast<const float4*>(
                &A[(size_t)(bm + r) * K + k0 + c4 * 4]);
            As[(c4*4 + 0) * PITCH + r] = __uint_as_float(f2tf32(v.x));
            As[(c4*4 + 1) * PITCH + r] = __uint_as_float(f2tf32(v.y));
            As[(c4*4 + 2) * PITCH + r] = __uint_as_float(f2tf32(v.z));
            As[(c4*4 + 3) * PITCH + r] = __uint_as_float(f2tf32(v.w));
        }
        // stage B tile (16 x 128) into Bs[k][n]
#pragma unroll
        for (int it = 0; it < 2; it++) {
            int i = tid + it * 256;
            int r = i >> 5, c4 = i & 31;
            float4 v = *reinterpret_cast<const float4*>(
                &W[(size_t)(k0 + r) * N + bn + c4 * 4]);
            float4 o;
            o.x = __uint_as_float(f2tf32(v.x));
            o.y = __uint_as_float(f2tf32(v.y));
            o.z = __uint_as_float(f2tf32(v.z));
            o.w = __uint_as_float(f2tf32(v.w));
            *reinterpret_cast<float4*>(&Bs[r * PITCH + c4 * 4]) = o;
        }
        __syncthreads();

#pragma unroll
        for (int kk = 0; kk < GBK; kk += 8) {
            uint32_t af[2][4];
#pragma unroll
            for (int mt = 0; mt < 2; mt++) {
                int row = wm + mt * 16 + grp;
                af[mt][0] = __float_as_uint(As[(kk + t4    ) * PITCH + row    ]);
                af[mt][1] = __float_as_uint(As[(kk + t4    ) * PITCH + row + 8]);
                af[mt][2] = __float_as_uint(As[(kk + t4 + 4) * PITCH + row    ]);
                af[mt][3] = __float_as_uint(As[(kk + t4 + 4) * PITCH + row + 8]);
            }
            uint32_t bf[8][2];
#pragma unroll
            for (int nt = 0; nt < 8; nt++) {
                int col = wn + nt * 8 + grp;
                bf[nt][0] = __float_as_uint(Bs[(kk + t4    ) * PITCH + col]);
                bf[nt][1] = __float_as_uint(Bs[(kk + t4 + 4) * PITCH + col]);
            }
#pragma unroll
            for (int mt = 0; mt < 2; mt++)
#pragma unroll
                for (int nt = 0; nt < 8; nt++) {
                    asm volatile(
                        "mma.sync.aligned.m16n8k8.row.col.f32.tf32.tf32.f32 "
                        "{%0,%1,%2,%3}, {%4,%5,%6,%7}, {%8,%9}, {%0,%1,%2,%3};\n"
                        : "+f"(acc[mt][nt][0]), "+f"(acc[mt][nt][1]),
                          "+f"(acc[mt][nt][2]), "+f"(acc[mt][nt][3])
                        : "r"(af[mt][0]), "r"(af[mt][1]), "r"(af[mt][2]), "r"(af[mt][3]),
                          "r"(bf[nt][0]), "r"(bf[nt][1]));
                }
        }
        __syncthreads();
    }

    // epilogue: (acc + bias)*s + b2  ==  acc*s + (bias*s + b2)
#pragma unroll
    for (int nt = 0; nt < 8; nt++) {
        int col = bn + wn + nt * 8 + t4 * 2;
        float s0 = bns[col],     s1 = bns[col + 1];
        float h0 = bias[col] * s0 + bnb[col];
        float h1 = bias[col + 1] * s1 + bnb[col + 1];
#pragma unroll
        for (int mt = 0; mt < 2; mt++) {
            int row = bm + wm + mt * 16 + grp;
            float2 r0, r1;
            r0.x = acc[mt][nt][0] * s0 + h0;
            r0.y = acc[mt][nt][1] * s1 + h1;
            r1.x = acc[mt][nt][2] * s0 + h0;
            r1.y = acc[mt][nt][3] * s1 + h1;
            *reinterpret_cast<float2*>(&Y[(size_t)row * N + col]) = r0;
            *reinterpret_cast<float2*>(&Y[(size_t)(row + 8) * N + col]) = r1;
        }
    }
}

// ---------------- fused attention ----------------
// grid: (7, 8, 64)  block: 256
#define QT 28
#define SPITCH 788          // 784 + 4 pad
#define KTILE 56
__global__ void __launch_bounds__(256)
attn_kernel(const float* __restrict__ attn_bias) {
    const int qt = blockIdx.x, h = blockIdx.y, b = blockIdx.z;
    extern __shared__ float sm[];
    float* sQ    = sm;                       // QT*16
    float* sS    = sQ + QT*16;               // QT*SPITCH
    float* sV    = sS + QT*SPITCH;           // KTILE*64
    float* sInv  = sV + KTILE*64;            // QT
    float* sBias = sInv + QT;                // NKEY
    const int tid = threadIdx.x;
    const int q0 = qt * QT;

    for (int i = tid; i < QT*KD; i += 256) {
        int q = i / KD, t = i % KD;
        sQ[i] = g_q[((size_t)(b*NQ) + q0 + q) * (NH*KD) + h*KD + t];
    }
    for (int i = tid; i < NKEY; i += 256) sBias[i] = attn_bias[h*NKEY + i];
    __syncthreads();

    // phase 1: S[q][j] = 0.25 * q.k + bias
    for (int j = tid; j < NKEY; j += 256) {
        float kr[KD];
        const float* kp = g_k + ((size_t)(b*NKEY) + j) * (NH*KD) + h*KD;
#pragma unroll
        for (int t = 0; t < KD; t++) kr[t] = kp[t];
        const int jx = j % RES, jy = j / RES;
#pragma unroll 4
        for (int q = 0; q < QT; q++) {
            const int qg = q0 + q;
            const int qx = 2*(qg % RES2), qy = 2*(qg / RES2);
            float s = 0.f;
#pragma unroll
            for (int t = 0; t < KD; t++) s += sQ[q*KD + t] * kr[t];
            const int dxa = qx > jx ? qx - jx : jx - qx;
            const int dya = qy > jy ? qy - jy : jy - qy;
            sS[q*SPITCH + j] = s * 0.25f + sBias[dxa*RES + dya];
        }
    }
    __syncthreads();

    // phase 2: row softmax
    const int warp = tid >> 5, lane = tid & 31;
    for (int r = warp; r < QT; r += 8) {
        float m = -1e30f;
        for (int j = lane; j < NKEY; j += 32) m = fmaxf(m, sS[r*SPITCH + j]);
#pragma unroll
        for (int o = 16; o > 0; o >>= 1) m = fmaxf(m, __shfl_xor_sync(0xffffffffu, m, o));
        float sum = 0.f;
        for (int j = lane; j < NKEY; j += 32) {
            float e = __expf(sS[r*SPITCH + j] - m);
            sS[r*SPITCH + j] = e;
            sum += e;
        }
#pragma unroll
        for (int o = 16; o > 0; o >>= 1) sum += __shfl_xor_sync(0xffffffffu, sum, o);
        if (lane == 0) sInv[r] = 1.f / sum;
    }
    __syncthreads();

    // phase 3: O = P @ V, + v_local, normalize
    const int d = tid & 63, qg4 = tid >> 6;
    float acc[7] = {};
    for (int kt = 0; kt < NKEY; kt += KTILE) {
        for (int i = tid; i < KTILE*64; i += 256) {
            int j = i >> 6, dd = i & 63;
            sV[i] = g_v[((size_t)(b*NKEY) + kt + j) * DH + h*DV + dd];
        }
        __syncthreads();
#pragma unroll
        for (int t = 0; t < 7; t++) {
            const int q = qg4*7 + t;
            float a = 0.f;
#pragma unroll 8
            for (int j = 0; j < KTILE; j++) a += sS[q*SPITCH + kt + j] * sV[j*64 + d];
            acc[t] += a;
        }
        __syncthreads();
    }
#pragma unroll
    for (int t = 0; t < 7; t++) {
        const int q = qg4*7 + t;
        const size_t o = ((size_t)(b*NQ) + q0 + q) * DH + h*DV + d;
        g_ao[o] = acc[t] * sInv[q] + g_vloc[o];
    }
}

// ---------------- launch ----------------
extern "C" void kernel_launch(void* const* d_in, const int* in_sizes, int n_in,
                              void* d_out, int out_size) {
    const float* x         = (const float*)d_in[0];
    const float* q_local_w = (const float*)d_in[1];
    const float* q_local_b = (const float*)d_in[2];
    const float* q_proj_w  = (const float*)d_in[3];
    const float* q_proj_b  = (const float*)d_in[4];
    const float* q_bn_s    = (const float*)d_in[5];
    const float* q_bn_b    = (const float*)d_in[6];
    const float* k_w       = (const float*)d_in[7];
    const float* k_b       = (const float*)d_in[8];
    const float* k_bn_s    = (const float*)d_in[9];
    const float* k_bn_b    = (const float*)d_in[10];
    const float* v_w       = (const float*)d_in[11];
    const float* v_b       = (const float*)d_in[12];
    const float* v_bn_s    = (const float*)d_in[13];
    const float* v_bn_b    = (const float*)d_in[14];
    const float* vloc_w    = (const float*)d_in[15];
    const float* vloc_b    = (const float*)d_in[16];
    const float* vloc_bn_s = (const float*)d_in[17];
    const float* vloc_bn_b = (const float*)d_in[18];
    const float* proj_w    = (const float*)d_in[19];
    const float* proj_b    = (const float*)d_in[20];
    const float* proj_bn_s = (const float*)d_in[21];
    const float* proj_bn_b = (const float*)d_in[22];
    const float* attn_bias = (const float*)d_in[23];
    float* out = (float*)d_out;

    float *p_qds, *p_q, *p_k, *p_v, *p_ao;
    cudaGetSymbolAddress((void**)&p_qds, g_qds);
    cudaGetSymbolAddress((void**)&p_q,   g_q);
    cudaGetSymbolAddress((void**)&p_k,   g_k);
    cudaGetSymbolAddress((void**)&p_v,   g_v);
    cudaGetSymbolAddress((void**)&p_ao,  g_ao);

    // 1. q local conv + subsample residual -> g_qds [12544, 384]
    {
        int total = BATCH * NQ * CIN;
        conv_q_kernel<<<(total + 255)/256, 256>>>(x, q_local_w, q_local_b);
    }
    // 2. q projection: g_qds @ q_proj_w -> g_q [12544, 128]
    {
        dim3 grid((NH*KD)/GBN, MQ/GBM);
        gemm_tf32_kernel<<<grid, 256>>>(p_qds, q_proj_w, q_proj_b, q_bn_s, q_bn_b, p_q,
                                        MQ, NH*KD, CIN);
    }
    // 3. k: x @ k_w -> g_k [50176, 128]
    {
        dim3 grid((NH*KD)/GBN, MK/GBM);
        gemm_tf32_kernel<<<grid, 256>>>(x, k_w, k_b, k_bn_s, k_bn_b, p_k,
                                        MK, NH*KD, CIN);
    }
    // 4. v: x @ v_w -> g_v [50176, 512]
    {
        dim3 grid(DH/GBN, MK/GBM);
        gemm_tf32_kernel<<<grid, 256>>>(x, v_w, v_b, v_bn_s, v_bn_b, p_v,
                                        MK, DH, CIN);
    }
    // 5. v_local conv -> g_vloc [12544, 512]
    {
        int total = BATCH * NQ * DH;
        conv_vloc_kernel<<<(total + 255)/256, 256>>>(vloc_w, vloc_b, vloc_bn_s, vloc_bn_b);
    }
    // 6. attention (+v_local) -> g_ao [12544, 512]
    {
        const int smem = (QT*KD + QT*SPITCH + KTILE*64 + QT + NKEY) * sizeof(float);
        cudaFuncSetAttribute(attn_kernel, cudaFuncAttributeMaxDynamicSharedMemorySize, smem);
        dim3 grid(NQ/QT, NH, BATCH);
        attn_kernel<<<grid, 256, smem>>>(attn_bias);
    }
    // 7. projection: g_ao @ proj_w -> out [12544, 768]
    {
        dim3 grid(COUT/GBN, MQ/GBM);
        gemm_tf32_kernel<<<grid, 256>>>(p_ao, proj_w, proj_b, proj_bn_s, proj_bn_b, out,
                                        MQ, COUT, DH);
    }
}

// round 6
// speedup vs baseline: 2.1722x; 1.3244x over previous
#include <cuda_runtime.h>
#include <cuda_bf16.h>
#include <cstdint>

// ---------------- problem constants ----------------
#define BATCH 64
#define RES 28
#define RES2 14
#define NH 8
#define KD 16
#define DV 64
#define DH 512
#define CIN 384
#define COUT 768
#define NKEY (RES*RES)      // 784
#define NQ (RES2*RES2)      // 196
#define MQ (BATCH*NQ)       // 12544
#define MK (BATCH*NKEY)     // 50176

// ---------------- device scratch ----------------
__device__ float g_qds[(size_t)MQ * CIN];      // 12544 x 384
__device__ float g_q  [(size_t)MQ * (NH*KD)];  // 12544 x 128
__device__ float g_k  [(size_t)MK * (NH*KD)];  // 50176 x 128
__device__ float g_v  [(size_t)MK * DH];       // 50176 x 512
__device__ float g_vloc[(size_t)MQ * DH];      // 12544 x 512
__device__ float g_ao [(size_t)MQ * DH];       // 12544 x 512

__device__ __forceinline__ uint32_t f2tf32(float f) {
    uint32_t r;
    asm("cvt.rna.tf32.f32 %0, %1;\n" : "=r"(r) : "f"(f));
    return r;
}

// ---------------- depthwise 3x3 stride-2 SAME conv + residual subsample (for q) ----
__global__ void conv_q_kernel(const float* __restrict__ x,
                              const float* __restrict__ w,
                              const float* __restrict__ bias) {
    int idx = blockIdx.x * blockDim.x + threadIdx.x;
    const int total = BATCH * NQ * CIN;
    if (idx >= total) return;
    int c  = idx % CIN;
    int p  = idx / CIN;
    int b  = p / NQ;
    int pp = p % NQ;
    int oy = pp / RES2, ox = pp % RES2;
    float acc = bias[c];
#pragma unroll
    for (int dy = 0; dy < 3; dy++) {
        int iy = 2*oy + dy;
        if (iy >= RES) continue;
#pragma unroll
        for (int dx = 0; dx < 3; dx++) {
            int ix = 2*ox + dx;
            if (ix >= RES) continue;
            acc += x[(((size_t)b*RES + iy)*RES + ix)*CIN + c] * w[(dy*3+dx)*CIN + c];
        }
    }
    acc += x[(((size_t)b*RES + 2*oy)*RES + 2*ox)*CIN + c];
    g_qds[idx] = acc;
}

// ---------------- depthwise 3x3 stride-2 SAME conv + BN (for v_local) ----------
__global__ void conv_vloc_kernel(const float* __restrict__ w,
                                 const float* __restrict__ bias,
                                 const float* __restrict__ bns,
                                 const float* __restrict__ bnb) {
    int idx = blockIdx.x * blockDim.x + threadIdx.x;
    const int total = BATCH * NQ * DH;
    if (idx >= total) return;
    int c  = idx % DH;
    int p  = idx / DH;
    int b  = p / NQ;
    int pp = p % NQ;
    int oy = pp / RES2, ox = pp % RES2;
    float acc = bias[c];
#pragma unroll
    for (int dy = 0; dy < 3; dy++) {
        int iy = 2*oy + dy;
        if (iy >= RES) continue;
#pragma unroll
        for (int dx = 0; dx < 3; dx++) {
            int ix = 2*ox + dx;
            if (ix >= RES) continue;
            acc += g_v[(((size_t)b*RES + iy)*RES + ix)*DH + c] * w[(dy*3+dx)*DH + c];
        }
    }
    g_vloc[idx] = acc * bns[c] + bnb[c];
}

// ---------------- tf32 tensor-core GEMM, double-buffered ----------
// Y[m,n] = (sum_k A[m,k]*W[k,n] + bias[n]) * s[n] + b2[n]
// requires M%128==0, N%128==0, K%16==0
#define GBM 128
#define GBN 128
#define GBK 16
#define PITCH 136

__global__ void __launch_bounds__(256)
gemm_tf32_kernel(const float* __restrict__ A, const float* __restrict__ W,
                 const float* __restrict__ bias, const float* __restrict__ bns,
                 const float* __restrict__ bnb, float* __restrict__ Y,
                 int M, int N, int K) {
    __shared__ float As[2][GBK * PITCH];   // [k][m]
    __shared__ float Bs[2][GBK * PITCH];   // [k][n]
    const int bm = blockIdx.y * GBM, bn = blockIdx.x * GBN;
    const int tid = threadIdx.x;
    const int warp = tid >> 5, lane = tid & 31;
    const int grp = lane >> 2, t4 = lane & 3;
    const int wm = (warp & 3) * 32;
    const int wn = (warp >> 2) * 64;

    // A staging indices: i = tid + it*256 ; r=i>>2 (row), c4=i&3 (k-quad)
    // B staging indices: r=i>>5 (k), c4=i&31 (n-quad)
    float4 ra[2], rb[2];

    float acc[2][8][4];
#pragma unroll
    for (int i = 0; i < 2; i++)
#pragma unroll
        for (int j = 0; j < 8; j++)
#pragma unroll
            for (int c = 0; c < 4; c++) acc[i][j][c] = 0.f;

    const int nk = K / GBK;

    // prologue: load tile 0
#pragma unroll
    for (int it = 0; it < 2; it++) {
        int i = tid + it * 256;
        ra[it] = *reinterpret_cast<const float4*>(&A[(size_t)(bm + (i >> 2)) * K + (i & 3) * 4]);
        rb[it] = *reinterpret_cast<const float4*>(&W[(size_t)(i >> 5) * N + bn + (i & 31) * 4]);
    }
#pragma unroll
    for (int it = 0; it < 2; it++) {
        int i = tid + it * 256;
        int rA = i >> 2, cA = i & 3;
        As[0][(cA*4 + 0) * PITCH + rA] = __uint_as_float(f2tf32(ra[it].x));
        As[0][(cA*4 + 1) * PITCH + rA] = __uint_as_float(f2tf32(ra[it].y));
        As[0][(cA*4 + 2) * PITCH + rA] = __uint_as_float(f2tf32(ra[it].z));
        As[0][(cA*4 + 3) * PITCH + rA] = __uint_as_float(f2tf32(ra[it].w));
        int rB = i >> 5, cB = i & 31;
        float4 o;
        o.x = __uint_as_float(f2tf32(rb[it].x));
        o.y = __uint_as_float(f2tf32(rb[it].y));
        o.z = __uint_as_float(f2tf32(rb[it].z));
        o.w = __uint_as_float(f2tf32(rb[it].w));
        *reinterpret_cast<float4*>(&Bs[0][rB * PITCH + cB * 4]) = o;
    }
    __syncthreads();

    int buf = 0;
    for (int ki = 0; ki < nk; ki++) {
        const bool nxt = (ki + 1) < nk;
        const int k0n = (ki + 1) * GBK;
        if (nxt) {
#pragma unroll
            for (int it = 0; it < 2; it++) {
                int i = tid + it * 256;
                ra[it] = *reinterpret_cast<const float4*>(&A[(size_t)(bm + (i >> 2)) * K + k0n + (i & 3) * 4]);
                rb[it] = *reinterpret_cast<const float4*>(&W[(size_t)(k0n + (i >> 5)) * N + bn + (i & 31) * 4]);
            }
        }

        const float* pA = As[buf];
        const float* pB = Bs[buf];
#pragma unroll
        for (int kk = 0; kk < GBK; kk += 8) {
            uint32_t af[2][4];
#pragma unroll
            for (int mt = 0; mt < 2; mt++) {
                int row = wm + mt * 16 + grp;
                af[mt][0] = __float_as_uint(pA[(kk + t4    ) * PITCH + row    ]);
                af[mt][1] = __float_as_uint(pA[(kk + t4    ) * PITCH + row + 8]);
                af[mt][2] = __float_as_uint(pA[(kk + t4 + 4) * PITCH + row    ]);
                af[mt][3] = __float_as_uint(pA[(kk + t4 + 4) * PITCH + row + 8]);
            }
            uint32_t bf[8][2];
#pragma unroll
            for (int nt = 0; nt < 8; nt++) {
                int col = wn + nt * 8 + grp;
                bf[nt][0] = __float_as_uint(pB[(kk + t4    ) * PITCH + col]);
                bf[nt][1] = __float_as_uint(pB[(kk + t4 + 4) * PITCH + col]);
            }
#pragma unroll
            for (int mt = 0; mt < 2; mt++)
#pragma unroll
                for (int nt = 0; nt < 8; nt++) {
                    asm volatile(
                        "mma.sync.aligned.m16n8k8.row.col.f32.tf32.tf32.f32 "
                        "{%0,%1,%2,%3}, {%4,%5,%6,%7}, {%8,%9}, {%0,%1,%2,%3};\n"
                        : "+f"(acc[mt][nt][0]), "+f"(acc[mt][nt][1]),
                          "+f"(acc[mt][nt][2]), "+f"(acc[mt][nt][3])
                        : "r"(af[mt][0]), "r"(af[mt][1]), "r"(af[mt][2]), "r"(af[mt][3]),
                          "r"(bf[nt][0]), "r"(bf[nt][1]));
                }
        }

        if (nxt) {
            float* qA = As[buf ^ 1];
            float* qB = Bs[buf ^ 1];
#pragma unroll
            for (int it = 0; it < 2; it++) {
                int i = tid + it * 256;
                int rA = i >> 2, cA = i & 3;
                qA[(cA*4 + 0) * PITCH + rA] = __uint_as_float(f2tf32(ra[it].x));
                qA[(cA*4 + 1) * PITCH + rA] = __uint_as_float(f2tf32(ra[it].y));
                qA[(cA*4 + 2) * PITCH + rA] = __uint_as_float(f2tf32(ra[it].z));
                qA[(cA*4 + 3) * PITCH + rA] = __uint_as_float(f2tf32(ra[it].w));
                int rB = i >> 5, cB = i & 31;
                float4 o;
                o.x = __uint_as_float(f2tf32(rb[it].x));
                o.y = __uint_as_float(f2tf32(rb[it].y));
                o.z = __uint_as_float(f2tf32(rb[it].z));
                o.w = __uint_as_float(f2tf32(rb[it].w));
                *reinterpret_cast<float4*>(&qB[rB * PITCH + cB * 4]) = o;
            }
        }
        __syncthreads();
        buf ^= 1;
    }

    // epilogue
#pragma unroll
    for (int nt = 0; nt < 8; nt++) {
        int col = bn + wn + nt * 8 + t4 * 2;
        float s0 = bns[col],     s1 = bns[col + 1];
        float h0 = bias[col] * s0 + bnb[col];
        float h1 = bias[col + 1] * s1 + bnb[col + 1];
#pragma unroll
        for (int mt = 0; mt < 2; mt++) {
            int row = bm + wm + mt * 16 + grp;
            float2 r0, r1;
            r0.x = acc[mt][nt][0] * s0 + h0;
            r0.y = acc[mt][nt][1] * s1 + h1;
            r1.x = acc[mt][nt][2] * s0 + h0;
            r1.y = acc[mt][nt][3] * s1 + h1;
            *reinterpret_cast<float2*>(&Y[(size_t)row * N + col]) = r0;
            *reinterpret_cast<float2*>(&Y[(size_t)(row + 8) * N + col]) = r1;
        }
    }
}

// ---------------- fused attention (tensor-core PV) ----------------
// grid: (14, 8, 64)  block: 256.  Each block: 14 query rows of one (b,h).
#define QT 14
#define SPITCH 788          // 784 + 4 pad; 788%32=20 -> conflict-free frag rows
#define VTILE 112
#define VPITCH 72           // 72%32=8 -> bank = grp + 8*t4, conflict-free
__global__ void __launch_bounds__(256)
attn_kernel(const float* __restrict__ attn_bias) {
    const int qt = blockIdx.x, h = blockIdx.y, b = blockIdx.z;
    extern __shared__ float sm[];
    float* sQ    = sm;                       // QT*16        = 224
    float* sS    = sQ + QT*KD;               // 16*SPITCH    = 12608
    float* sV    = sS + 16*SPITCH;           // VTILE*VPITCH = 8064
    float* sInv  = sV + VTILE*VPITCH;        // 16
    float* sBias = sInv + 16;                // 784
    const int tid = threadIdx.x;
    const int q0 = qt * QT;

    // stage Q, bias; zero S pad rows 14-15
    for (int i = tid; i < QT*KD; i += 256) {
        int q = i / KD, t = i % KD;
        sQ[i] = g_q[((size_t)(b*NQ) + q0 + q) * (NH*KD) + h*KD + t];
    }
    for (int i = tid; i < NKEY; i += 256) sBias[i] = attn_bias[h*NKEY + i];
    for (int i = tid; i < 2*SPITCH; i += 256) sS[14*SPITCH + i] = 0.f;
    __syncthreads();

    // phase 1: S[q][j] = 0.25 * q.k + bias  (scalar)
    for (int j = tid; j < NKEY; j += 256) {
        float kr[KD];
        const float4* kp = reinterpret_cast<const float4*>(
            g_k + ((size_t)(b*NKEY) + j) * (NH*KD) + h*KD);
#pragma unroll
        for (int t = 0; t < 4; t++) {
            float4 v = kp[t];
            kr[t*4+0] = v.x; kr[t*4+1] = v.y; kr[t*4+2] = v.z; kr[t*4+3] = v.w;
        }
        const int jx = j % RES, jy = j / RES;
#pragma unroll 2
        for (int q = 0; q < QT; q++) {
            const int qg = q0 + q;
            const int qx = 2*(qg % RES2), qy = 2*(qg / RES2);
            float s = 0.f;
#pragma unroll
            for (int t = 0; t < KD; t++) s += sQ[q*KD + t] * kr[t];
            const int dxa = qx > jx ? qx - jx : jx - qx;
            const int dya = qy > jy ? qy - jy : jy - qy;
            sS[q*SPITCH + j] = s * 0.25f + sBias[dxa*RES + dya];
        }
    }
    __syncthreads();

    // phase 2: row softmax; store exp pre-rounded to tf32
    const int warp = tid >> 5, lane = tid & 31;
    for (int r = warp; r < QT; r += 8) {
        float m = -1e30f;
        for (int j = lane; j < NKEY; j += 32) m = fmaxf(m, sS[r*SPITCH + j]);
#pragma unroll
        for (int o = 16; o > 0; o >>= 1) m = fmaxf(m, __shfl_xor_sync(0xffffffffu, m, o));
        float sum = 0.f;
        for (int j = lane; j < NKEY; j += 32) {
            float e = __uint_as_float(f2tf32(__expf(sS[r*SPITCH + j] - m)));
            sS[r*SPITCH + j] = e;
            sum += e;
        }
#pragma unroll
        for (int o = 16; o > 0; o >>= 1) sum += __shfl_xor_sync(0xffffffffu, sum, o);
        if (lane == 0) sInv[r] = 1.f / sum;
    }
    __syncthreads();

    // phase 3: O[16,64] = P[16,784] @ V[784,64] via m16n8k8.tf32
    // warp w owns output columns [w*8, w*8+8)
    const int grp = lane >> 2, t4 = lane & 3;
    float c[4] = {0.f, 0.f, 0.f, 0.f};
    for (int kt = 0; kt < NKEY; kt += VTILE) {
        // stage V tile (convert to tf32), pitch 72
#pragma unroll
        for (int it = 0; it < 7; it++) {
            int i = tid + it * 256;
            int j = i >> 4, d4 = i & 15;
            float4 v = *reinterpret_cast<const float4*>(
                &g_v[((size_t)(b*NKEY) + kt + j) * DH + h*DV + d4*4]);
            float* dst = &sV[j*VPITCH + d4*4];
            dst[0] = __uint_as_float(f2tf32(v.x));
            dst[1] = __uint_as_float(f2tf32(v.y));
            dst[2] = __uint_as_float(f2tf32(v.z));
            dst[3] = __uint_as_float(f2tf32(v.w));
        }
        __syncthreads();
#pragma unroll
        for (int c8 = 0; c8 < VTILE/8; c8++) {
            const int kb = kt + c8*8;
            uint32_t a0 = __float_as_uint(sS[ grp      * SPITCH + kb + t4    ]);
            uint32_t a1 = __float_as_uint(sS[(grp + 8) * SPITCH + kb + t4    ]);
            uint32_t a2 = __float_as_uint(sS[ grp      * SPITCH + kb + t4 + 4]);
            uint32_t a3 = __float_as_uint(sS[(grp + 8) * SPITCH + kb + t4 + 4]);
            uint32_t b0 = __float_as_uint(sV[(c8*8 + t4    ) * VPITCH + warp*8 + grp]);
            uint32_t b1 = __float_as_uint(sV[(c8*8 + t4 + 4) * VPITCH + warp*8 + grp]);
            asm volatile(
                "mma.sync.aligned.m16n8k8.row.col.f32.tf32.tf32.f32 "
                "{%0,%1,%2,%3}, {%4,%5,%6,%7}, {%8,%9}, {%0,%1,%2,%3};\n"
                : "+f"(c[0]), "+f"(c[1]), "+f"(c[2]), "+f"(c[3])
                : "r"(a0), "r"(a1), "r"(a2), "r"(a3), "r"(b0), "r"(b1));
        }
        __syncthreads();
    }

    // epilogue: rows grp (<14 always) and grp+8 (store if <14)
    {
        const int col = warp*8 + t4*2;
        const int r0 = grp, r1 = grp + 8;
        size_t o0 = ((size_t)(b*NQ) + q0 + r0) * DH + h*DV + col;
        float inv0 = sInv[r0];
        g_ao[o0]     = c[0] * inv0 + g_vloc[o0];
        g_ao[o0 + 1] = c[1] * inv0 + g_vloc[o0 + 1];
        if (r1 < QT) {
            size_t o1 = ((size_t)(b*NQ) + q0 + r1) * DH + h*DV + col;
            float inv1 = sInv[r1];
            g_ao[o1]     = c[2] * inv1 + g_vloc[o1];
            g_ao[o1 + 1] = c[3] * inv1 + g_vloc[o1 + 1];
        }
    }
}

// ---------------- launch ----------------
extern "C" void kernel_launch(void* const* d_in, const int* in_sizes, int n_in,
                              void* d_out, int out_size) {
    const float* x         = (const float*)d_in[0];
    const float* q_local_w = (const float*)d_in[1];
    const float* q_local_b = (const float*)d_in[2];
    const float* q_proj_w  = (const float*)d_in[3];
    const float* q_proj_b  = (const float*)d_in[4];
    const float* q_bn_s    = (const float*)d_in[5];
    const float* q_bn_b    = (const float*)d_in[6];
    const float* k_w       = (const float*)d_in[7];
    const float* k_b       = (const float*)d_in[8];
    const float* k_bn_s    = (const float*)d_in[9];
    const float* k_bn_b    = (const float*)d_in[10];
    const float* v_w       = (const float*)d_in[11];
    const float* v_b       = (const float*)d_in[12];
    const float* v_bn_s    = (const float*)d_in[13];
    const float* v_bn_b    = (const float*)d_in[14];
    const float* vloc_w    = (const float*)d_in[15];
    const float* vloc_b    = (const float*)d_in[16];
    const float* vloc_bn_s = (const float*)d_in[17];
    const float* vloc_bn_b = (const float*)d_in[18];
    const float* proj_w    = (const float*)d_in[19];
    const float* proj_b    = (const float*)d_in[20];
    const float* proj_bn_s = (const float*)d_in[21];
    const float* proj_bn_b = (const float*)d_in[22];
    const float* attn_bias = (const float*)d_in[23];
    float* out = (float*)d_out;

    float *p_qds, *p_q, *p_k, *p_v, *p_ao;
    cudaGetSymbolAddress((void**)&p_qds, g_qds);
    cudaGetSymbolAddress((void**)&p_q,   g_q);
    cudaGetSymbolAddress((void**)&p_k,   g_k);
    cudaGetSymbolAddress((void**)&p_v,   g_v);
    cudaGetSymbolAddress((void**)&p_ao,  g_ao);

    // 1. q local conv + subsample residual -> g_qds
    {
        int total = BATCH * NQ * CIN;
        conv_q_kernel<<<(total + 255)/256, 256>>>(x, q_local_w, q_local_b);
    }
    // 2. q projection
    {
        dim3 grid((NH*KD)/GBN, MQ/GBM);
        gemm_tf32_kernel<<<grid, 256>>>(p_qds, q_proj_w, q_proj_b, q_bn_s, q_bn_b, p_q,
                                        MQ, NH*KD, CIN);
    }
    // 3. k
    {
        dim3 grid((NH*KD)/GBN, MK/GBM);
        gemm_tf32_kernel<<<grid, 256>>>(x, k_w, k_b, k_bn_s, k_bn_b, p_k,
                                        MK, NH*KD, CIN);
    }
    // 4. v
    {
        dim3 grid(DH/GBN, MK/GBM);
        gemm_tf32_kernel<<<grid, 256>>>(x, v_w, v_b, v_bn_s, v_bn_b, p_v,
                                        MK, DH, CIN);
    }
    // 5. v_local conv
    {
        int total = BATCH * NQ * DH;
        conv_vloc_kernel<<<(total + 255)/256, 256>>>(vloc_w, vloc_b, vloc_bn_s, vloc_bn_b);
    }
    // 6. attention (+v_local)
    {
        const int smem = (QT*KD + 16*SPITCH + VTILE*VPITCH + 16 + NKEY) * sizeof(float);
        cudaFuncSetAttribute(attn_kernel, cudaFuncAttributeMaxDynamicSharedMemorySize, smem);
        dim3 grid(NQ/QT, NH, BATCH);
        attn_kernel<<<grid, 256, smem>>>(attn_bias);
    }
    // 7. projection
    {
        dim3 grid(COUT/GBN, MQ/GBM);
        gemm_tf32_kernel<<<grid, 256>>>(p_ao, proj_w, proj_b, proj_bn_s, proj_bn_b, out,
                                        MQ, COUT, DH);
    }
}

// round 8
// speedup vs baseline: 3.3917x; 1.5614x over previous
#include <cuda_runtime.h>
#include <cuda_fp16.h>
#include <cuda_bf16.h>
#include <cstdint>

// ---------------- problem constants ----------------
#define BATCH 64
#define RES 28
#define RES2 14
#define NH 8
#define KD 16
#define DV 64
#define DH 512
#define CIN 384
#define COUT 768
#define NKEY (RES*RES)      // 784
#define NQ (RES2*RES2)      // 196
#define MQ (BATCH*NQ)       // 12544
#define MK (BATCH*NKEY)     // 50176

// ---------------- device scratch ----------------
__device__ float g_qds[(size_t)MQ * CIN];      // 12544 x 384
__device__ float g_q  [(size_t)MQ * (NH*KD)];  // 12544 x 128
__device__ float g_k  [(size_t)MK * (NH*KD)];  // 50176 x 128
__device__ float g_v  [(size_t)MK * DH];       // 50176 x 512
__device__ float g_vloc[(size_t)MQ * DH];      // 12544 x 512
__device__ float g_ao [(size_t)MQ * DH];       // 12544 x 512

__device__ __forceinline__ uint32_t f2tf32(float f) {
    uint32_t r;
    asm("cvt.rna.tf32.f32 %0, %1;\n" : "=r"(r) : "f"(f));
    return r;
}

// ---------------- depthwise 3x3 stride-2 SAME conv + residual subsample (for q) ----
__global__ void conv_q_kernel(const float* __restrict__ x,
                              const float* __restrict__ w,
                              const float* __restrict__ bias) {
    int idx = blockIdx.x * blockDim.x + threadIdx.x;
    const int total = BATCH * NQ * CIN;
    if (idx >= total) return;
    int c  = idx % CIN;
    int p  = idx / CIN;
    int b  = p / NQ;
    int pp = p % NQ;
    int oy = pp / RES2, ox = pp % RES2;
    float acc = bias[c];
#pragma unroll
    for (int dy = 0; dy < 3; dy++) {
        int iy = 2*oy + dy;
        if (iy >= RES) continue;
#pragma unroll
        for (int dx = 0; dx < 3; dx++) {
            int ix = 2*ox + dx;
            if (ix >= RES) continue;
            acc += x[(((size_t)b*RES + iy)*RES + ix)*CIN + c] * w[(dy*3+dx)*CIN + c];
        }
    }
    acc += x[(((size_t)b*RES + 2*oy)*RES + 2*ox)*CIN + c];
    g_qds[idx] = acc;
}

// ---------------- depthwise 3x3 stride-2 SAME conv + BN (for v_local) ----------
__global__ void conv_vloc_kernel(const float* __restrict__ w,
                                 const float* __restrict__ bias,
                                 const float* __restrict__ bns,
                                 const float* __restrict__ bnb) {
    int idx = blockIdx.x * blockDim.x + threadIdx.x;
    const int total = BATCH * NQ * DH;
    if (idx >= total) return;
    int c  = idx % DH;
    int p  = idx / DH;
    int b  = p / NQ;
    int pp = p % NQ;
    int oy = pp / RES2, ox = pp % RES2;
    float acc = bias[c];
#pragma unroll
    for (int dy = 0; dy < 3; dy++) {
        int iy = 2*oy + dy;
        if (iy >= RES) continue;
#pragma unroll
        for (int dx = 0; dx < 3; dx++) {
            int ix = 2*ox + dx;
            if (ix >= RES) continue;
            acc += g_v[(((size_t)b*RES + iy)*RES + ix)*DH + c] * w[(dy*3+dx)*DH + c];
        }
    }
    g_vloc[idx] = acc * bns[c] + bnb[c];
}

// ---------------- tf32 tensor-core GEMM, double-buffered, packed-A fragments ----
// Y[m,n] = (sum_k A[m,k]*W[k,n] + bias[n]) * s[n] + b2[n]
// requires M%128==0, N%128==0, K%16==0
#define GBM 128
#define GBN 128
#define GBK 16
#define PITCH 136

// A fragment-packed layout: float4 index = ((tile16*2 + z)*8 + grp)*4 + (t4 ^ (grp&3))
// element within float4 = (khi*2 + mhi) ^ ((grp>>2)<<1)
__device__ __forceinline__ void stage_A_packed(float* dstf, int i, float4 ra) {
    int rA = i >> 2, cA = i & 3;
    int t16 = rA >> 4, mhi = (rA >> 3) & 1, gA = rA & 7;
    int zA = cA >> 1, khi = cA & 1;
    int qd = ((khi << 1) | mhi) ^ ((gA >> 2) << 1);
    int base4 = (((t16*2 + zA)*8 + gA) << 2);
    float vals[4] = {__uint_as_float(f2tf32(ra.x)), __uint_as_float(f2tf32(ra.y)),
                     __uint_as_float(f2tf32(ra.z)), __uint_as_float(f2tf32(ra.w))};
#pragma unroll
    for (int j = 0; j < 4; j++) {
        int slot = j ^ (gA & 3);
        dstf[((base4 + slot) << 2) + qd] = vals[j];
    }
}

__device__ __forceinline__ void stage_B(float* dst, int i, float4 rb) {
    int rB = i >> 5, cB = i & 31;
    float4 o;
    o.x = __uint_as_float(f2tf32(rb.x));
    o.y = __uint_as_float(f2tf32(rb.y));
    o.z = __uint_as_float(f2tf32(rb.z));
    o.w = __uint_as_float(f2tf32(rb.w));
    *reinterpret_cast<float4*>(&dst[rB * PITCH + cB * 4]) = o;
}

__global__ void __launch_bounds__(256)
gemm_tf32_kernel(const float* __restrict__ A, const float* __restrict__ W,
                 const float* __restrict__ bias, const float* __restrict__ bns,
                 const float* __restrict__ bnb, float* __restrict__ Y,
                 int M, int N, int K) {
    __shared__ float4 As4[2][512];         // packed A fragments, 8KB each
    __shared__ float  Bs[2][GBK * PITCH];  // [k][n]
    const int bm = blockIdx.y * GBM, bn = blockIdx.x * GBN;
    const int tid = threadIdx.x;
    const int warp = tid >> 5, lane = tid & 31;
    const int grp = lane >> 2, t4 = lane & 3;
    const int wm16 = (warp & 3) * 2;       // tile16 base for this warp
    const int wn = (warp >> 2) * 64;
    const int xsw = (grp >> 2) << 1;
    const int aslot = t4 ^ (grp & 3);

    float4 ra[2], rb[2];
    float acc[2][8][4];
#pragma unroll
    for (int i = 0; i < 2; i++)
#pragma unroll
        for (int j = 0; j < 8; j++)
#pragma unroll
            for (int c = 0; c < 4; c++) acc[i][j][c] = 0.f;

    const int nk = K / GBK;

    // prologue: load + stage tile 0
#pragma unroll
    for (int it = 0; it < 2; it++) {
        int i = tid + it * 256;
        ra[it] = *reinterpret_cast<const float4*>(&A[(size_t)(bm + (i >> 2)) * K + (i & 3) * 4]);
        rb[it] = *reinterpret_cast<const float4*>(&W[(size_t)(i >> 5) * N + bn + (i & 31) * 4]);
    }
#pragma unroll
    for (int it = 0; it < 2; it++) {
        int i = tid + it * 256;
        stage_A_packed((float*)As4[0], i, ra[it]);
        stage_B(Bs[0], i, rb[it]);
    }
    __syncthreads();

    int buf = 0;
    for (int ki = 0; ki < nk; ki++) {
        const bool nxt = (ki + 1) < nk;
        const int k0n = (ki + 1) * GBK;
        if (nxt) {
#pragma unroll
            for (int it = 0; it < 2; it++) {
                int i = tid + it * 256;
                ra[it] = *reinterpret_cast<const float4*>(&A[(size_t)(bm + (i >> 2)) * K + k0n + (i & 3) * 4]);
                rb[it] = *reinterpret_cast<const float4*>(&W[(size_t)(k0n + (i >> 5)) * N + bn + (i & 31) * 4]);
            }
        }

        const float4* pA = As4[buf];
        const float*  pB = Bs[buf];
#pragma unroll
        for (int z = 0; z < 2; z++) {       // kk = z*8
            uint32_t af[2][4];
#pragma unroll
            for (int mt = 0; mt < 2; mt++) {
                float4 v = pA[(((wm16 + mt)*2 + z)*8 + grp)*4 + aslot];
                float e[4] = {v.x, v.y, v.z, v.w};
                af[mt][0] = __float_as_uint(e[0 ^ xsw]);
                af[mt][1] = __float_as_uint(e[1 ^ xsw]);
                af[mt][2] = __float_as_uint(e[2 ^ xsw]);
                af[mt][3] = __float_as_uint(e[3 ^ xsw]);
            }
            const int kk = z * 8;
            uint32_t bf[8][2];
#pragma unroll
            for (int nt = 0; nt < 8; nt++) {
                int col = wn + nt * 8 + grp;
                bf[nt][0] = __float_as_uint(pB[(kk + t4    ) * PITCH + col]);
                bf[nt][1] = __float_as_uint(pB[(kk + t4 + 4) * PITCH + col]);
            }
#pragma unroll
            for (int mt = 0; mt < 2; mt++)
#pragma unroll
                for (int nt = 0; nt < 8; nt++) {
                    asm volatile(
                        "mma.sync.aligned.m16n8k8.row.col.f32.tf32.tf32.f32 "
                        "{%0,%1,%2,%3}, {%4,%5,%6,%7}, {%8,%9}, {%0,%1,%2,%3};\n"
                        : "+f"(acc[mt][nt][0]), "+f"(acc[mt][nt][1]),
                          "+f"(acc[mt][nt][2]), "+f"(acc[mt][nt][3])
                        : "r"(af[mt][0]), "r"(af[mt][1]), "r"(af[mt][2]), "r"(af[mt][3]),
                          "r"(bf[nt][0]), "r"(bf[nt][1]));
                }
        }

        if (nxt) {
#pragma unroll
            for (int it = 0; it < 2; it++) {
                int i = tid + it * 256;
                stage_A_packed((float*)As4[buf ^ 1], i, ra[it]);
                stage_B(Bs[buf ^ 1], i, rb[it]);
            }
        }
        __syncthreads();
        buf ^= 1;
    }

    // epilogue
#pragma unroll
    for (int nt = 0; nt < 8; nt++) {
        int col = bn + wn + nt * 8 + t4 * 2;
        float s0 = bns[col],     s1 = bns[col + 1];
        float h0 = bias[col] * s0 + bnb[col];
        float h1 = bias[col + 1] * s1 + bnb[col + 1];
#pragma unroll
        for (int mt = 0; mt < 2; mt++) {
            int row = bm + (wm16 + mt) * 16 + grp;
            float2 r0, r1;
            r0.x = acc[mt][nt][0] * s0 + h0;
            r0.y = acc[mt][nt][1] * s1 + h1;
            r1.x = acc[mt][nt][2] * s0 + h0;
            r1.y = acc[mt][nt][3] * s1 + h1;
            *reinterpret_cast<float2*>(&Y[(size_t)row * N + col]) = r0;
            *reinterpret_cast<float2*>(&Y[(size_t)(row + 8) * N + col]) = r1;
        }
    }
}

// ---------------- fused attention (f16 tensor-core PV, QT=28) ----------------
// grid: (7, 8, 64)  block: 256.  Each block: 28 query rows of one (b,h).
#define QT 28
#define SPH 792             // half pitch for S (28+4 pad rows x 792)
#define VTILE 112
#define VP 68               // half pitch for V tile [k][col]
#define ATTN_SMEM ((QT*KD + NKEY + 32)*4 + (32*SPH + VTILE*VP)*2)

__global__ void __launch_bounds__(256)
attn_kernel(const float* __restrict__ attn_bias) {
    const int qt = blockIdx.x, h = blockIdx.y, b = blockIdx.z;
    extern __shared__ char smraw[];
    float*  sQ    = (float*)smraw;                              // QT*16 = 448 f
    float*  sBias = sQ + QT*KD;                                 // 784 f
    float*  sInv  = sBias + NKEY;                               // 32 f
    __half* sS    = (__half*)(smraw + (QT*KD + NKEY + 32)*4);   // 32*SPH h
    __half* sV    = sS + 32*SPH;                                // VTILE*VP h
    const int tid = threadIdx.x;
    const int q0 = qt * QT;

    // stage Q, bias; zero S pad rows 28..31
    for (int i = tid; i < QT*KD; i += 256) {
        int q = i / KD, t = i % KD;
        sQ[i] = g_q[((size_t)(b*NQ) + q0 + q) * (NH*KD) + h*KD + t];
    }
    for (int i = tid; i < NKEY; i += 256) sBias[i] = attn_bias[h*NKEY + i];
    for (int i = tid; i < 4*SPH; i += 256) sS[28*SPH + i] = __ushort_as_half(0);
    __syncthreads();

    // phase 1: S[q][j] = 0.25 * q.k + bias  -> f16
    for (int j = tid; j < NKEY; j += 256) {
        float kr[KD];
        const float4* kp = reinterpret_cast<const float4*>(
            g_k + ((size_t)(b*NKEY) + j) * (NH*KD) + h*KD);
#pragma unroll
        for (int t = 0; t < 4; t++) {
            float4 v = kp[t];
            kr[t*4+0] = v.x; kr[t*4+1] = v.y; kr[t*4+2] = v.z; kr[t*4+3] = v.w;
        }
        const int jx = j % RES, jy = j / RES;
#pragma unroll 2
        for (int q = 0; q < QT; q++) {
            const int qg = q0 + q;
            const int qx = 2*(qg % RES2), qy = 2*(qg / RES2);
            float s = 0.f;
#pragma unroll
            for (int t = 0; t < KD; t++) s += sQ[q*KD + t] * kr[t];
            const int dxa = qx > jx ? qx - jx : jx - qx;
            const int dya = qy > jy ? qy - jy : jy - qy;
            sS[q*SPH + j] = __float2half(s * 0.25f + sBias[dxa*RES + dya]);
        }
    }
    __syncthreads();

    // phase 2: row softmax; store exp as f16, sum the rounded values
    const int warp = tid >> 5, lane = tid & 31;
    for (int r = warp; r < QT; r += 8) {
        float m = -1e30f;
        for (int j = lane; j < NKEY; j += 32) m = fmaxf(m, __half2float(sS[r*SPH + j]));
#pragma unroll
        for (int o = 16; o > 0; o >>= 1) m = fmaxf(m, __shfl_xor_sync(0xffffffffu, m, o));
        float sum = 0.f;
        for (int j = lane; j < NKEY; j += 32) {
            float e = __expf(__half2float(sS[r*SPH + j]) - m);
            __half he = __float2half(e);
            sS[r*SPH + j] = he;
            sum += __half2float(he);
        }
#pragma unroll
        for (int o = 16; o > 0; o >>= 1) sum += __shfl_xor_sync(0xffffffffu, sum, o);
        if (lane == 0) sInv[r] = 1.f / sum;
    }
    __syncthreads();

    // phase 3: O[32,64] = P[32,784] @ V[784,64] via mma.m16n8k16.f16
    // warp w owns output columns [w*8, w*8+8)
    const int grp = lane >> 2, t4 = lane & 3;
    const int col = warp*8 + grp;
    float c[2][4] = {{0.f,0.f,0.f,0.f},{0.f,0.f,0.f,0.f}};
    const unsigned short* sVus = reinterpret_cast<const unsigned short*>(sV);

    for (int kt = 0; kt < NKEY; kt += VTILE) {
        // stage V tile as f16 [k][col], pitch VP
#pragma unroll
        for (int it = 0; it < 7; it++) {
            int i = tid + it * 256;
            int j = i >> 4, d4 = i & 15;
            float4 v = *reinterpret_cast<const float4*>(
                &g_v[((size_t)(b*NKEY) + kt + j) * DH + h*DV + d4*4]);
            __half2 h01 = __floats2half2_rn(v.x, v.y);
            __half2 h23 = __floats2half2_rn(v.z, v.w);
            uint2 u;
            u.x = *reinterpret_cast<uint32_t*>(&h01);
            u.y = *reinterpret_cast<uint32_t*>(&h23);
            *reinterpret_cast<uint2*>(&sV[j*VP + d4*4]) = u;
        }
        __syncthreads();

#pragma unroll
        for (int ks = 0; ks < VTILE; ks += 16) {
            const int kg = kt + ks;
            // B fragment: rows 2t4,2t4+1 (b0) and 2t4+8,2t4+9 (b1), col = warp*8+grp
            uint32_t b0 = (uint32_t)sVus[(ks + 2*t4    )*VP + col]
                        | ((uint32_t)sVus[(ks + 2*t4 + 1)*VP + col] << 16);
            uint32_t b1 = (uint32_t)sVus[(ks + 2*t4 + 8)*VP + col]
                        | ((uint32_t)sVus[(ks + 2*t4 + 9)*VP + col] << 16);
#pragma unroll
            for (int mt = 0; mt < 2; mt++) {
                const int row = mt*16 + grp;
                uint32_t a0 = *reinterpret_cast<const uint32_t*>(&sS[ row      *SPH + kg + 2*t4    ]);
                uint32_t a1 = *reinterpret_cast<const uint32_t*>(&sS[(row + 8) *SPH + kg + 2*t4    ]);
                uint32_t a2 = *reinterpret_cast<const uint32_t*>(&sS[ row      *SPH + kg + 2*t4 + 8]);
                uint32_t a3 = *reinterpret_cast<const uint32_t*>(&sS[(row + 8) *SPH + kg + 2*t4 + 8]);
                asm volatile(
                    "mma.sync.aligned.m16n8k16.row.col.f32.f16.f16.f32 "
                    "{%0,%1,%2,%3}, {%4,%5,%6,%7}, {%8,%9}, {%0,%1,%2,%3};\n"
                    : "+f"(c[mt][0]), "+f"(c[mt][1]), "+f"(c[mt][2]), "+f"(c[mt][3])
                    : "r"(a0), "r"(a1), "r"(a2), "r"(a3), "r"(b0), "r"(b1));
            }
        }
        __syncthreads();
    }

    // epilogue: c[mt][0,1] -> row mt*16+grp ; c[mt][2,3] -> row mt*16+8+grp
    {
        const int ocol = warp*8 + 2*t4;
#pragma unroll
        for (int mt = 0; mt < 2; mt++) {
            int r0 = mt*16 + grp;
            size_t o0 = ((size_t)(b*NQ) + q0 + r0) * DH + h*DV + ocol;
            float inv0 = sInv[r0];
            g_ao[o0]     = c[mt][0] * inv0 + g_vloc[o0];
            g_ao[o0 + 1] = c[mt][1] * inv0 + g_vloc[o0 + 1];
            int r1 = mt*16 + 8 + grp;
            if (r1 < QT) {
                size_t o1 = ((size_t)(b*NQ) + q0 + r1) * DH + h*DV + ocol;
                float inv1 = sInv[r1];
                g_ao[o1]     = c[mt][2] * inv1 + g_vloc[o1];
                g_ao[o1 + 1] = c[mt][3] * inv1 + g_vloc[o1 + 1];
            }
        }
    }
}

// ---------------- launch ----------------
extern "C" void kernel_launch(void* const* d_in, const int* in_sizes, int n_in,
                              void* d_out, int out_size) {
    const float* x         = (const float*)d_in[0];
    const float* q_local_w = (const float*)d_in[1];
    const float* q_local_b = (const float*)d_in[2];
    const float* q_proj_w  = (const float*)d_in[3];
    const float* q_proj_b  = (const float*)d_in[4];
    const float* q_bn_s    = (const float*)d_in[5];
    const float* q_bn_b    = (const float*)d_in[6];
    const float* k_w       = (const float*)d_in[7];
    const float* k_b       = (const float*)d_in[8];
    const float* k_bn_s    = (const float*)d_in[9];
    const float* k_bn_b    = (const float*)d_in[10];
    const float* v_w       = (const float*)d_in[11];
    const float* v_b       = (const float*)d_in[12];
    const float* v_bn_s    = (const float*)d_in[13];
    const float* v_bn_b    = (const float*)d_in[14];
    const float* vloc_w    = (const float*)d_in[15];
    const float* vloc_b    = (const float*)d_in[16];
    const float* vloc_bn_s = (const float*)d_in[17];
    const float* vloc_bn_b = (const float*)d_in[18];
    const float* proj_w    = (const float*)d_in[19];
    const float* proj_b    = (const float*)d_in[20];
    const float* proj_bn_s = (const float*)d_in[21];
    const float* proj_bn_b = (const float*)d_in[22];
    const float* attn_bias = (const float*)d_in[23];
    float* out = (float*)d_out;

    float *p_qds, *p_q, *p_k, *p_v, *p_ao;
    cudaGetSymbolAddress((void**)&p_qds, g_qds);
    cudaGetSymbolAddress((void**)&p_q,   g_q);
    cudaGetSymbolAddress((void**)&p_k,   g_k);
    cudaGetSymbolAddress((void**)&p_v,   g_v);
    cudaGetSymbolAddress((void**)&p_ao,  g_ao);

    // 1. q local conv + subsample residual -> g_qds
    {
        int total = BATCH * NQ * CIN;
        conv_q_kernel<<<(total + 255)/256, 256>>>(x, q_local_w, q_local_b);
    }
    // 2. q projection
    {
        dim3 grid((NH*KD)/GBN, MQ/GBM);
        gemm_tf32_kernel<<<grid, 256>>>(p_qds, q_proj_w, q_proj_b, q_bn_s, q_bn_b, p_q,
                                        MQ, NH*KD, CIN);
    }
    // 3. k
    {
        dim3 grid((NH*KD)/GBN, MK/GBM);
        gemm_tf32_kernel<<<grid, 256>>>(x, k_w, k_b, k_bn_s, k_bn_b, p_k,
                                        MK, NH*KD, CIN);
    }
    // 4. v
    {
        dim3 grid(DH/GBN, MK/GBM);
        gemm_tf32_kernel<<<grid, 256>>>(x, v_w, v_b, v_bn_s, v_bn_b, p_v,
                                        MK, DH, CIN);
    }
    // 5. v_local conv
    {
        int total = BATCH * NQ * DH;
        conv_vloc_kernel<<<(total + 255)/256, 256>>>(vloc_w, vloc_b, vloc_bn_s, vloc_bn_b);
    }
    // 6. attention (+v_local)
    {
        cudaFuncSetAttribute(attn_kernel, cudaFuncAttributeMaxDynamicSharedMemorySize, ATTN_SMEM);
        dim3 grid(NQ/QT, NH, BATCH);
        attn_kernel<<<grid, 256, ATTN_SMEM>>>(attn_bias);
    }
    // 7. projection
    {
        dim3 grid(COUT/GBN, MQ/GBM);
        gemm_tf32_kernel<<<grid, 256>>>(p_ao, proj_w, proj_b, proj_bn_s, proj_bn_b, out,
                                        MQ, COUT, DH);
    }
}

// round 11
// speedup vs baseline: 4.4462x; 1.3109x over previous
#include <cuda_runtime.h>
#include <cuda_fp16.h>
#include <cuda_bf16.h>
#include <cstdint>

// ---------------- problem constants ----------------
#define BATCH 64
#define RES 28
#define RES2 14
#define NH 8
#define KD 16
#define DV 64
#define DH 512
#define CIN 384
#define COUT 768
#define NKEY (RES*RES)      // 784
#define NQ (RES2*RES2)      // 196
#define MQ (BATCH*NQ)       // 12544
#define MK (BATCH*NKEY)     // 50176

// ---------------- device scratch ----------------
__device__ float g_qds[(size_t)MQ * CIN];      // 12544 x 384
__device__ float g_q  [(size_t)MQ * (NH*KD)];  // 12544 x 128
__device__ float g_k  [(size_t)MK * (NH*KD)];  // 50176 x 128
__device__ float g_v  [(size_t)MK * DH];       // 50176 x 512
__device__ float g_vloc[(size_t)MQ * DH];      // 12544 x 512
__device__ float g_ao [(size_t)MQ * DH];       // 12544 x 512

__device__ __forceinline__ uint32_t h2u(__half2 h) {
    return *reinterpret_cast<uint32_t*>(&h);
}

// ---------------- depthwise 3x3 stride-2 SAME conv + residual subsample (for q) ----
__global__ void conv_q_kernel(const float* __restrict__ x,
                              const float* __restrict__ w,
                              const float* __restrict__ bias) {
    int idx = blockIdx.x * blockDim.x + threadIdx.x;
    const int total = BATCH * NQ * CIN;
    if (idx >= total) return;
    int c  = idx % CIN;
    int p  = idx / CIN;
    int b  = p / NQ;
    int pp = p % NQ;
    int oy = pp / RES2, ox = pp % RES2;
    float acc = bias[c];
#pragma unroll
    for (int dy = 0; dy < 3; dy++) {
        int iy = 2*oy + dy;
        if (iy >= RES) continue;
#pragma unroll
        for (int dx = 0; dx < 3; dx++) {
            int ix = 2*ox + dx;
            if (ix >= RES) continue;
            acc += x[(((size_t)b*RES + iy)*RES + ix)*CIN + c] * w[(dy*3+dx)*CIN + c];
        }
    }
    acc += x[(((size_t)b*RES + 2*oy)*RES + 2*ox)*CIN + c];
    g_qds[idx] = acc;
}

// ---------------- depthwise 3x3 stride-2 SAME conv + BN (for v_local) ----------
__global__ void conv_vloc_kernel(const float* __restrict__ w,
                                 const float* __restrict__ bias,
                                 const float* __restrict__ bns,
                                 const float* __restrict__ bnb) {
    int idx = blockIdx.x * blockDim.x + threadIdx.x;
    const int total = BATCH * NQ * DH;
    if (idx >= total) return;
    int c  = idx % DH;
    int p  = idx / DH;
    int b  = p / NQ;
    int pp = p % NQ;
    int oy = pp / RES2, ox = pp % RES2;
    float acc = bias[c];
#pragma unroll
    for (int dy = 0; dy < 3; dy++) {
        int iy = 2*oy + dy;
        if (iy >= RES) continue;
#pragma unroll
        for (int dx = 0; dx < 3; dx++) {
            int ix = 2*ox + dx;
            if (ix >= RES) continue;
            acc += g_v[(((size_t)b*RES + iy)*RES + ix)*DH + c] * w[(dy*3+dx)*DH + c];
        }
    }
    g_vloc[idx] = acc * bns[c] + bnb[c];
}

// ---------------- f16 tensor-core GEMM (m16n8k16), double-buffered ----------
// Y[m,n] = (sum_k A[m,k]*W[k,n] + bias[n]) * s[n] + b2[n]
// requires M%128==0, N%128==0, K%16==0
#define GBM 128
#define GBN 128
#define GBK 16
#define APITCH 24   // halves per A row (16 + 8 pad); bank = (12*row + t4) % 32, conflict-free
#define BPITCH 136  // uint32 per B k-pair row (128 + 8 pad)

// A tile: [m][k] halves.  thread: row = tid>>1, kh = (tid&1)*8; one uint4 store (8 halves)
__device__ __forceinline__ void stage_Ah(__half* dst, int tid, float4 r0, float4 r1) {
    int row = tid >> 1, kh = (tid & 1) * 8;
    uint4 u;
    u.x = h2u(__floats2half2_rn(r0.x, r0.y));
    u.y = h2u(__floats2half2_rn(r0.z, r0.w));
    u.z = h2u(__floats2half2_rn(r1.x, r1.y));
    u.w = h2u(__floats2half2_rn(r1.z, r1.w));
    *reinterpret_cast<uint4*>(&dst[row * APITCH + kh]) = u;
}

// B tile: k-pair interleaved uint32 [k/2][n]: lo = B[2k'][n], hi = B[2k'+1][n]
// thread: k2 = tid>>5, n4 = (tid&31)*4; one uint4 store (4 uint32)
__device__ __forceinline__ void stage_Bh(uint32_t* dst, int tid, float4 re, float4 ro) {
    int k2 = tid >> 5, n4 = (tid & 31) * 4;
    uint4 u;
    u.x = h2u(__floats2half2_rn(re.x, ro.x));
    u.y = h2u(__floats2half2_rn(re.y, ro.y));
    u.z = h2u(__floats2half2_rn(re.z, ro.z));
    u.w = h2u(__floats2half2_rn(re.w, ro.w));
    *reinterpret_cast<uint4*>(&dst[k2 * BPITCH + n4]) = u;
}

__global__ void __launch_bounds__(256, 2)
gemm_f16_kernel(const float* __restrict__ A, const float* __restrict__ W,
                const float* __restrict__ bias, const float* __restrict__ bns,
                const float* __restrict__ bnb, float* __restrict__ Y,
                int M, int N, int K) {
    __shared__ __half   As[2][GBM * APITCH];   // 6144 B each
    __shared__ uint32_t Bs[2][8 * BPITCH];     // 4352 B each
    const int bm = blockIdx.y * GBM, bn = blockIdx.x * GBN;
    const int tid = threadIdx.x;
    const int warp = tid >> 5, lane = tid & 31;
    const int grp = lane >> 2, t4 = lane & 3;
    const int wm = (warp & 3) * 32;
    const int wn = (warp >> 2) * 64;

    // staging source indices
    const int arow = tid >> 1, akh = (tid & 1) * 8;
    const int bk2 = tid >> 5, bn4 = (tid & 31) * 4;

    float4 ra0, ra1, rbe, rbo;
    float acc[2][8][4];
#pragma unroll
    for (int i = 0; i < 2; i++)
#pragma unroll
        for (int j = 0; j < 8; j++)
#pragma unroll
            for (int c = 0; c < 4; c++) acc[i][j][c] = 0.f;

    const int nk = K / GBK;

    // prologue: load + stage tile 0
    ra0 = *reinterpret_cast<const float4*>(&A[(size_t)(bm + arow) * K + akh]);
    ra1 = *reinterpret_cast<const float4*>(&A[(size_t)(bm + arow) * K + akh + 4]);
    rbe = *reinterpret_cast<const float4*>(&W[(size_t)(2*bk2    ) * N + bn + bn4]);
    rbo = *reinterpret_cast<const float4*>(&W[(size_t)(2*bk2 + 1) * N + bn + bn4]);
    stage_Ah(As[0], tid, ra0, ra1);
    stage_Bh(Bs[0], tid, rbe, rbo);
    __syncthreads();

    int buf = 0;
    for (int ki = 0; ki < nk; ki++) {
        const bool nxt = (ki + 1) < nk;
        if (nxt) {
            const int k0n = (ki + 1) * GBK;
            ra0 = *reinterpret_cast<const float4*>(&A[(size_t)(bm + arow) * K + k0n + akh]);
            ra1 = *reinterpret_cast<const float4*>(&A[(size_t)(bm + arow) * K + k0n + akh + 4]);
            rbe = *reinterpret_cast<const float4*>(&W[(size_t)(k0n + 2*bk2    ) * N + bn + bn4]);
            rbo = *reinterpret_cast<const float4*>(&W[(size_t)(k0n + 2*bk2 + 1) * N + bn + bn4]);
        }

        const __half*   pA = As[buf];
        const uint32_t* pB = Bs[buf];
        uint32_t af[2][4];
#pragma unroll
        for (int mt = 0; mt < 2; mt++) {
            int row = wm + mt * 16 + grp;
            af[mt][0] = *reinterpret_cast<const uint32_t*>(&pA[ row      * APITCH + 2*t4    ]);
            af[mt][1] = *reinterpret_cast<const uint32_t*>(&pA[(row + 8) * APITCH + 2*t4    ]);
            af[mt][2] = *reinterpret_cast<const uint32_t*>(&pA[ row      * APITCH + 2*t4 + 8]);
            af[mt][3] = *reinterpret_cast<const uint32_t*>(&pA[(row + 8) * APITCH + 2*t4 + 8]);
        }
        uint32_t bf[8][2];
#pragma unroll
        for (int nt = 0; nt < 8; nt++) {
            int col = wn + nt * 8 + grp;
            bf[nt][0] = pB[(t4    ) * BPITCH + col];
            bf[nt][1] = pB[(t4 + 4) * BPITCH + col];
        }
#pragma unroll
        for (int mt = 0; mt < 2; mt++)
#pragma unroll
            for (int nt = 0; nt < 8; nt++) {
                asm volatile(
                    "mma.sync.aligned.m16n8k16.row.col.f32.f16.f16.f32 "
                    "{%0,%1,%2,%3}, {%4,%5,%6,%7}, {%8,%9}, {%0,%1,%2,%3};\n"
                    : "+f"(acc[mt][nt][0]), "+f"(acc[mt][nt][1]),
                      "+f"(acc[mt][nt][2]), "+f"(acc[mt][nt][3])
                    : "r"(af[mt][0]), "r"(af[mt][1]), "r"(af[mt][2]), "r"(af[mt][3]),
                      "r"(bf[nt][0]), "r"(bf[nt][1]));
            }

        if (nxt) {
            stage_Ah(As[buf ^ 1], tid, ra0, ra1);
            stage_Bh(Bs[buf ^ 1], tid, rbe, rbo);
        }
        __syncthreads();
        buf ^= 1;
    }

    // epilogue: (acc + bias)*s + b2  ==  acc*s + (bias*s + b2)
#pragma unroll
    for (int nt = 0; nt < 8; nt++) {
        int col = bn + wn + nt * 8 + t4 * 2;
        float s0 = bns[col],     s1 = bns[col + 1];
        float h0 = bias[col] * s0 + bnb[col];
        float h1 = bias[col + 1] * s1 + bnb[col + 1];
#pragma unroll
        for (int mt = 0; mt < 2; mt++) {
            int row = bm + wm + mt * 16 + grp;
            float2 r0, r1;
            r0.x = acc[mt][nt][0] * s0 + h0;
            r0.y = acc[mt][nt][1] * s1 + h1;
            r1.x = acc[mt][nt][2] * s0 + h0;
            r1.y = acc[mt][nt][3] * s1 + h1;
            *reinterpret_cast<float2*>(&Y[(size_t)row * N + col]) = r0;
            *reinterpret_cast<float2*>(&Y[(size_t)(row + 8) * N + col]) = r1;
        }
    }
}

// ---------------- fused attention (f16 tensor-core PV, QT=28) ----------------
// grid: (7, 8, 64)  block: 256.  Each block: 28 query rows of one (b,h).
#define QT 28
#define SPH 792             // half pitch for S (28+4 pad rows x 792)
#define VTILE 112
#define VP 68               // half pitch for V tile [k][col]
#define ATTN_SMEM ((QT*KD + NKEY + 32)*4 + (32*SPH + VTILE*VP)*2)

__global__ void __launch_bounds__(256)
attn_kernel(const float* __restrict__ attn_bias) {
    const int qt = blockIdx.x, h = blockIdx.y, b = blockIdx.z;
    extern __shared__ char smraw[];
    float*  sQ    = (float*)smraw;                              // QT*16 = 448 f
    float*  sBias = sQ + QT*KD;                                 // 784 f
    float*  sInv  = sBias + NKEY;                               // 32 f
    __half* sS    = (__half*)(smraw + (QT*KD + NKEY + 32)*4);   // 32*SPH h
    __half* sV    = sS + 32*SPH;                                // VTILE*VP h
    const int tid = threadIdx.x;
    const int q0 = qt * QT;

    // stage Q, bias; zero S pad rows 28..31
    for (int i = tid; i < QT*KD; i += 256) {
        int q = i / KD, t = i % KD;
        sQ[i] = g_q[((size_t)(b*NQ) + q0 + q) * (NH*KD) + h*KD + t];
    }
    for (int i = tid; i < NKEY; i += 256) sBias[i] = attn_bias[h*NKEY + i];
    for (int i = tid; i < 4*SPH; i += 256) sS[28*SPH + i] = __ushort_as_half(0);
    __syncthreads();

    // phase 1: S[q][j] = 0.25 * q.k + bias  -> f16
    for (int j = tid; j < NKEY; j += 256) {
        float kr[KD];
        const float4* kp = reinterpret_cast<const float4*>(
            g_k + ((size_t)(b*NKEY) + j) * (NH*KD) + h*KD);
#pragma unroll
        for (int t = 0; t < 4; t++) {
            float4 v = kp[t];
            kr[t*4+0] = v.x; kr[t*4+1] = v.y; kr[t*4+2] = v.z; kr[t*4+3] = v.w;
        }
        const int jx = j % RES, jy = j / RES;
#pragma unroll 2
        for (int q = 0; q < QT; q++) {
            const int qg = q0 + q;
            const int qx = 2*(qg % RES2), qy = 2*(qg / RES2);
            float s = 0.f;
#pragma unroll
            for (int t = 0; t < KD; t++) s += sQ[q*KD + t] * kr[t];
            const int dxa = qx > jx ? qx - jx : jx - qx;
            const int dya = qy > jy ? qy - jy : jy - qy;
            sS[q*SPH + j] = __float2half(s * 0.25f + sBias[dxa*RES + dya]);
        }
    }
    __syncthreads();

    // phase 2: row softmax; store exp as f16, sum the rounded values
    const int warp = tid >> 5, lane = tid & 31;
    for (int r = warp; r < QT; r += 8) {
        float m = -1e30f;
        for (int j = lane; j < NKEY; j += 32) m = fmaxf(m, __half2float(sS[r*SPH + j]));
#pragma unroll
        for (int o = 16; o > 0; o >>= 1) m = fmaxf(m, __shfl_xor_sync(0xffffffffu, m, o));
        float sum = 0.f;
        for (int j = lane; j < NKEY; j += 32) {
            float e = __expf(__half2float(sS[r*SPH + j]) - m);
            __half he = __float2half(e);
            sS[r*SPH + j] = he;
            sum += __half2float(he);
        }
#pragma unroll
        for (int o = 16; o > 0; o >>= 1) sum += __shfl_xor_sync(0xffffffffu, sum, o);
        if (lane == 0) sInv[r] = 1.f / sum;
    }
    __syncthreads();

    // phase 3: O[32,64] = P[32,784] @ V[784,64] via mma.m16n8k16.f16
    // warp w owns output columns [w*8, w*8+8)
    const int grp = lane >> 2, t4 = lane & 3;
    const int col = warp*8 + grp;
    float c[2][4] = {{0.f,0.f,0.f,0.f},{0.f,0.f,0.f,0.f}};
    const unsigned short* sVus = reinterpret_cast<const unsigned short*>(sV);

    for (int kt = 0; kt < NKEY; kt += VTILE) {
        // stage V tile as f16 [k][col], pitch VP
#pragma unroll
        for (int it = 0; it < 7; it++) {
            int i = tid + it * 256;
            int j = i >> 4, d4 = i & 15;
            float4 v = *reinterpret_cast<const float4*>(
                &g_v[((size_t)(b*NKEY) + kt + j) * DH + h*DV + d4*4]);
            __half2 h01 = __floats2half2_rn(v.x, v.y);
            __half2 h23 = __floats2half2_rn(v.z, v.w);
            uint2 u;
            u.x = h2u(h01);
            u.y = h2u(h23);
            *reinterpret_cast<uint2*>(&sV[j*VP + d4*4]) = u;
        }
        __syncthreads();

#pragma unroll
        for (int ks = 0; ks < VTILE; ks += 16) {
            const int kg = kt + ks;
            // B fragment: rows 2t4,2t4+1 (b0) and 2t4+8,2t4+9 (b1), col = warp*8+grp
            uint32_t b0 = (uint32_t)sVus[(ks + 2*t4    )*VP + col]
                        | ((uint32_t)sVus[(ks + 2*t4 + 1)*VP + col] << 16);
            uint32_t b1 = (uint32_t)sVus[(ks + 2*t4 + 8)*VP + col]
                        | ((uint32_t)sVus[(ks + 2*t4 + 9)*VP + col] << 16);
#pragma unroll
            for (int mt = 0; mt < 2; mt++) {
                const int row = mt*16 + grp;
                uint32_t a0 = *reinterpret_cast<const uint32_t*>(&sS[ row      *SPH + kg + 2*t4    ]);
                uint32_t a1 = *reinterpret_cast<const uint32_t*>(&sS[(row + 8) *SPH + kg + 2*t4    ]);
                uint32_t a2 = *reinterpret_cast<const uint32_t*>(&sS[ row      *SPH + kg + 2*t4 + 8]);
                uint32_t a3 = *reinterpret_cast<const uint32_t*>(&sS[(row + 8) *SPH + kg + 2*t4 + 8]);
                asm volatile(
                    "mma.sync.aligned.m16n8k16.row.col.f32.f16.f16.f32 "
                    "{%0,%1,%2,%3}, {%4,%5,%6,%7}, {%8,%9}, {%0,%1,%2,%3};\n"
                    : "+f"(c[mt][0]), "+f"(c[mt][1]), "+f"(c[mt][2]), "+f"(c[mt][3])
                    : "r"(a0), "r"(a1), "r"(a2), "r"(a3), "r"(b0), "r"(b1));
            }
        }
        __syncthreads();
    }

    // epilogue: c[mt][0,1] -> row mt*16+grp ; c[mt][2,3] -> row mt*16+8+grp
    {
        const int ocol = warp*8 + 2*t4;
#pragma unroll
        for (int mt = 0; mt < 2; mt++) {
            int r0 = mt*16 + grp;
            size_t o0 = ((size_t)(b*NQ) + q0 + r0) * DH + h*DV + ocol;
            float inv0 = sInv[r0];
            g_ao[o0]     = c[mt][0] * inv0 + g_vloc[o0];
            g_ao[o0 + 1] = c[mt][1] * inv0 + g_vloc[o0 + 1];
            int r1 = mt*16 + 8 + grp;
            if (r1 < QT) {
                size_t o1 = ((size_t)(b*NQ) + q0 + r1) * DH + h*DV + ocol;
                float inv1 = sInv[r1];
                g_ao[o1]     = c[mt][2] * inv1 + g_vloc[o1];
                g_ao[o1 + 1] = c[mt][3] * inv1 + g_vloc[o1 + 1];
            }
        }
    }
}

// ---------------- launch ----------------
extern "C" void kernel_launch(void* const* d_in, const int* in_sizes, int n_in,
                              void* d_out, int out_size) {
    const float* x         = (const float*)d_in[0];
    const float* q_local_w = (const float*)d_in[1];
    const float* q_local_b = (const float*)d_in[2];
    const float* q_proj_w  = (const float*)d_in[3];
    const float* q_proj_b  = (const float*)d_in[4];
    const float* q_bn_s    = (const float*)d_in[5];
    const float* q_bn_b    = (const float*)d_in[6];
    const float* k_w       = (const float*)d_in[7];
    const float* k_b       = (const float*)d_in[8];
    const float* k_bn_s    = (const float*)d_in[9];
    const float* k_bn_b    = (const float*)d_in[10];
    const float* v_w       = (const float*)d_in[11];
    const float* v_b       = (const float*)d_in[12];
    const float* v_bn_s    = (const float*)d_in[13];
    const float* v_bn_b    = (const float*)d_in[14];
    const float* vloc_w    = (const float*)d_in[15];
    const float* vloc_b    = (const float*)d_in[16];
    const float* vloc_bn_s = (const float*)d_in[17];
    const float* vloc_bn_b = (const float*)d_in[18];
    const float* proj_w    = (const float*)d_in[19];
    const float* proj_b    = (const float*)d_in[20];
    const float* proj_bn_s = (const float*)d_in[21];
    const float* proj_bn_b = (const float*)d_in[22];
    const float* attn_bias = (const float*)d_in[23];
    float* out = (float*)d_out;

    float *p_qds, *p_q, *p_k, *p_v, *p_ao;
    cudaGetSymbolAddress((void**)&p_qds, g_qds);
    cudaGetSymbolAddress((void**)&p_q,   g_q);
    cudaGetSymbolAddress((void**)&p_k,   g_k);
    cudaGetSymbolAddress((void**)&p_v,   g_v);
    cudaGetSymbolAddress((void**)&p_ao,  g_ao);

    // 1. q local conv + subsample residual -> g_qds
    {
        int total = BATCH * NQ * CIN;
        conv_q_kernel<<<(total + 255)/256, 256>>>(x, q_local_w, q_local_b);
    }
    // 2. q projection
    {
        dim3 grid((NH*KD)/GBN, MQ/GBM);
        gemm_f16_kernel<<<grid, 256>>>(p_qds, q_proj_w, q_proj_b, q_bn_s, q_bn_b, p_q,
                                       MQ, NH*KD, CIN);
    }
    // 3. k
    {
        dim3 grid((NH*KD)/GBN, MK/GBM);
        gemm_f16_kernel<<<grid, 256>>>(x, k_w, k_b, k_bn_s, k_bn_b, p_k,
                                       MK, NH*KD, CIN);
    }
    // 4. v
    {
        dim3 grid(DH/GBN, MK/GBM);
        gemm_f16_kernel<<<grid, 256>>>(x, v_w, v_b, v_bn_s, v_bn_b, p_v,
                                       MK, DH, CIN);
    }
    // 5. v_local conv
    {
        int total = BATCH * NQ * DH;
        conv_vloc_kernel<<<(total + 255)/256, 256>>>(vloc_w, vloc_b, vloc_bn_s, vloc_bn_b);
    }
    // 6. attention (+v_local)
    {
        cudaFuncSetAttribute(attn_kernel, cudaFuncAttributeMaxDynamicSharedMemorySize, ATTN_SMEM);
        dim3 grid(NQ/QT, NH, BATCH);
        attn_kernel<<<grid, 256, ATTN_SMEM>>>(attn_bias);
    }
    // 7. projection
    {
        dim3 grid(COUT/GBN, MQ/GBM);
        gemm_f16_kernel<<<grid, 256>>>(p_ao, proj_w, proj_b, proj_bn_s, proj_bn_b, out,
                                       MQ, COUT, DH);
    }
}

// round 12
// speedup vs baseline: 4.4705x; 1.0055x over previous
#include <cuda_runtime.h>
#include <cuda_fp16.h>
#include <cuda_bf16.h>
#include <cstdint>

// ---------------- problem constants ----------------
#define BATCH 64
#define RES 28
#define RES2 14
#define NH 8
#define KD 16
#define DV 64
#define DH 512
#define CIN 384
#define COUT 768
#define NKEY (RES*RES)      // 784
#define NQ (RES2*RES2)      // 196
#define MQ (BATCH*NQ)       // 12544
#define MK (BATCH*NKEY)     // 50176

// ---------------- device scratch ----------------
__device__ float g_qds[(size_t)MQ * CIN];      // 12544 x 384
__device__ float g_q  [(size_t)MQ * (NH*KD)];  // 12544 x 128
__device__ float g_k  [(size_t)MK * (NH*KD)];  // 50176 x 128
__device__ float g_v  [(size_t)MK * DH];       // 50176 x 512
__device__ float g_vloc[(size_t)MQ * DH];      // 12544 x 512
__device__ float g_ao [(size_t)MQ * DH];       // 12544 x 512

__device__ __forceinline__ uint32_t h2u(__half2 h) {
    return *reinterpret_cast<uint32_t*>(&h);
}
__device__ __forceinline__ uint32_t smaddr(const void* p) {
    return (uint32_t)__cvta_generic_to_shared(p);
}
__device__ __forceinline__ void ldsm_x4(uint32_t& r0, uint32_t& r1, uint32_t& r2, uint32_t& r3, uint32_t a) {
    asm volatile("ldmatrix.sync.aligned.m8n8.x4.shared.b16 {%0,%1,%2,%3}, [%4];"
                 : "=r"(r0), "=r"(r1), "=r"(r2), "=r"(r3) : "r"(a));
}
__device__ __forceinline__ void ldsm_x4t(uint32_t& r0, uint32_t& r1, uint32_t& r2, uint32_t& r3, uint32_t a) {
    asm volatile("ldmatrix.sync.aligned.m8n8.x4.trans.shared.b16 {%0,%1,%2,%3}, [%4];"
                 : "=r"(r0), "=r"(r1), "=r"(r2), "=r"(r3) : "r"(a));
}
__device__ __forceinline__ void ldsm_x2t(uint32_t& r0, uint32_t& r1, uint32_t a) {
    asm volatile("ldmatrix.sync.aligned.m8n8.x2.trans.shared.b16 {%0,%1}, [%2];"
                 : "=r"(r0), "=r"(r1) : "r"(a));
}

// ---------------- depthwise 3x3 stride-2 SAME conv + residual subsample (for q) ----
__global__ void conv_q_kernel(const float* __restrict__ x,
                              const float* __restrict__ w,
                              const float* __restrict__ bias) {
    int idx = blockIdx.x * blockDim.x + threadIdx.x;
    const int total = BATCH * NQ * CIN;
    if (idx >= total) return;
    int c  = idx % CIN;
    int p  = idx / CIN;
    int b  = p / NQ;
    int pp = p % NQ;
    int oy = pp / RES2, ox = pp % RES2;
    float acc = bias[c];
#pragma unroll
    for (int dy = 0; dy < 3; dy++) {
        int iy = 2*oy + dy;
        if (iy >= RES) continue;
#pragma unroll
        for (int dx = 0; dx < 3; dx++) {
            int ix = 2*ox + dx;
            if (ix >= RES) continue;
            acc += x[(((size_t)b*RES + iy)*RES + ix)*CIN + c] * w[(dy*3+dx)*CIN + c];
        }
    }
    acc += x[(((size_t)b*RES + 2*oy)*RES + 2*ox)*CIN + c];
    g_qds[idx] = acc;
}

// ---------------- depthwise 3x3 stride-2 SAME conv + BN (for v_local) ----------
__global__ void conv_vloc_kernel(const float* __restrict__ w,
                                 const float* __restrict__ bias,
                                 const float* __restrict__ bns,
                                 const float* __restrict__ bnb) {
    int idx = blockIdx.x * blockDim.x + threadIdx.x;
    const int total = BATCH * NQ * DH;
    if (idx >= total) return;
    int c  = idx % DH;
    int p  = idx / DH;
    int b  = p / NQ;
    int pp = p % NQ;
    int oy = pp / RES2, ox = pp % RES2;
    float acc = bias[c];
#pragma unroll
    for (int dy = 0; dy < 3; dy++) {
        int iy = 2*oy + dy;
        if (iy >= RES) continue;
#pragma unroll
        for (int dx = 0; dx < 3; dx++) {
            int ix = 2*ox + dx;
            if (ix >= RES) continue;
            acc += g_v[(((size_t)b*RES + iy)*RES + ix)*DH + c] * w[(dy*3+dx)*DH + c];
        }
    }
    g_vloc[idx] = acc * bns[c] + bnb[c];
}

// ---------------- f16 tensor-core GEMM (m16n8k16 + ldmatrix), double-buffered ----
// Y[m,n] = (sum_k A[m,k]*W[k,n] + bias[n]) * s[n] + b2[n]
// requires M%128==0, N%128==0, K%16==0
#define GBM 128
#define GBN 128
#define GBK 16
#define APITCH 24   // halves per A row; 48B stride -> LDSM banks 12r mod 32, distinct
#define BPH 136     // halves per B k-row; 272B stride -> LDSM banks 4k, distinct

// A tile [m][k] halves: thread row=tid>>1, kh=(tid&1)*8; one STS.128
__device__ __forceinline__ void stage_Ah(__half* dst, int row, int kh, float4 r0, float4 r1) {
    uint4 u;
    u.x = h2u(__floats2half2_rn(r0.x, r0.y));
    u.y = h2u(__floats2half2_rn(r0.z, r0.w));
    u.z = h2u(__floats2half2_rn(r1.x, r1.y));
    u.w = h2u(__floats2half2_rn(r1.z, r1.w));
    *reinterpret_cast<uint4*>(&dst[row * APITCH + kh]) = u;
}
// B tile [k][n] halves: thread krow=tid>>4, n8=(tid&15)*8; one STS.128
__device__ __forceinline__ void stage_Bh(__half* dst, int krow, int n8, float4 r0, float4 r1) {
    uint4 u;
    u.x = h2u(__floats2half2_rn(r0.x, r0.y));
    u.y = h2u(__floats2half2_rn(r0.z, r0.w));
    u.z = h2u(__floats2half2_rn(r1.x, r1.y));
    u.w = h2u(__floats2half2_rn(r1.z, r1.w));
    *reinterpret_cast<uint4*>(&dst[krow * BPH + n8]) = u;
}

__global__ void __launch_bounds__(256, 2)
gemm_f16_kernel(const float* __restrict__ A, const float* __restrict__ W,
                const float* __restrict__ bias, const float* __restrict__ bns,
                const float* __restrict__ bnb, float* __restrict__ Y,
                int M, int N, int K) {
    __shared__ __half As[2][GBM * APITCH];   // 6144 B each
    __shared__ __half Bs[2][GBK * BPH];      // 4352 B each
    const int bm = blockIdx.y * GBM, bn = blockIdx.x * GBN;
    const int tid = threadIdx.x;
    const int warp = tid >> 5, lane = tid & 31;
    const int grp = lane >> 2, t4 = lane & 3;
    const int wm = (warp & 3) * 32;
    const int wn = (warp >> 2) * 64;

    // staging source indices
    const int arow = tid >> 1, akh = (tid & 1) * 8;
    const int bkr = tid >> 4, bn8 = (tid & 15) * 8;
    // LDSM lane address components
    const int l16 = lane & 15, lhi8 = (lane >> 4) * 8;

    float4 ra0, ra1, rb0, rb1;
    float acc[2][8][4];
#pragma unroll
    for (int i = 0; i < 2; i++)
#pragma unroll
        for (int j = 0; j < 8; j++)
#pragma unroll
            for (int c = 0; c < 4; c++) acc[i][j][c] = 0.f;

    const int nk = K / GBK;

    // prologue: load + stage tile 0
    ra0 = *reinterpret_cast<const float4*>(&A[(size_t)(bm + arow) * K + akh]);
    ra1 = *reinterpret_cast<const float4*>(&A[(size_t)(bm + arow) * K + akh + 4]);
    rb0 = *reinterpret_cast<const float4*>(&W[(size_t)bkr * N + bn + bn8]);
    rb1 = *reinterpret_cast<const float4*>(&W[(size_t)bkr * N + bn + bn8 + 4]);
    stage_Ah(As[0], arow, akh, ra0, ra1);
    stage_Bh(Bs[0], bkr, bn8, rb0, rb1);
    __syncthreads();

    int buf = 0;
    for (int ki = 0; ki < nk; ki++) {
        const bool nxt = (ki + 1) < nk;
        if (nxt) {
            const int k0n = (ki + 1) * GBK;
            ra0 = *reinterpret_cast<const float4*>(&A[(size_t)(bm + arow) * K + k0n + akh]);
            ra1 = *reinterpret_cast<const float4*>(&A[(size_t)(bm + arow) * K + k0n + akh + 4]);
            rb0 = *reinterpret_cast<const float4*>(&W[(size_t)(k0n + bkr) * N + bn + bn8]);
            rb1 = *reinterpret_cast<const float4*>(&W[(size_t)(k0n + bkr) * N + bn + bn8 + 4]);
        }

        const __half* pA = As[buf];
        const __half* pB = Bs[buf];
        uint32_t af[2][4];
#pragma unroll
        for (int mt = 0; mt < 2; mt++)
            ldsm_x4(af[mt][0], af[mt][1], af[mt][2], af[mt][3],
                    smaddr(&pA[(wm + mt*16 + l16) * APITCH + lhi8]));
        uint32_t bf[8][2];
#pragma unroll
        for (int nt2 = 0; nt2 < 4; nt2++) {
            uint32_t q0, q1, q2, q3;
            ldsm_x4t(q0, q1, q2, q3,
                     smaddr(&pB[l16 * BPH + wn + nt2*16 + lhi8]));
            bf[2*nt2    ][0] = q0; bf[2*nt2    ][1] = q1;
            bf[2*nt2 + 1][0] = q2; bf[2*nt2 + 1][1] = q3;
        }
#pragma unroll
        for (int mt = 0; mt < 2; mt++)
#pragma unroll
            for (int nt = 0; nt < 8; nt++) {
                asm volatile(
                    "mma.sync.aligned.m16n8k16.row.col.f32.f16.f16.f32 "
                    "{%0,%1,%2,%3}, {%4,%5,%6,%7}, {%8,%9}, {%0,%1,%2,%3};\n"
                    : "+f"(acc[mt][nt][0]), "+f"(acc[mt][nt][1]),
                      "+f"(acc[mt][nt][2]), "+f"(acc[mt][nt][3])
                    : "r"(af[mt][0]), "r"(af[mt][1]), "r"(af[mt][2]), "r"(af[mt][3]),
                      "r"(bf[nt][0]), "r"(bf[nt][1]));
            }

        if (nxt) {
            stage_Ah(As[buf ^ 1], arow, akh, ra0, ra1);
            stage_Bh(Bs[buf ^ 1], bkr, bn8, rb0, rb1);
        }
        __syncthreads();
        buf ^= 1;
    }

    // epilogue: (acc + bias)*s + b2  ==  acc*s + (bias*s + b2)
#pragma unroll
    for (int nt = 0; nt < 8; nt++) {
        int col = bn + wn + nt * 8 + t4 * 2;
        float s0 = bns[col],     s1 = bns[col + 1];
        float h0 = bias[col] * s0 + bnb[col];
        float h1 = bias[col + 1] * s1 + bnb[col + 1];
#pragma unroll
        for (int mt = 0; mt < 2; mt++) {
            int row = bm + wm + mt * 16 + grp;
            float2 r0, r1;
            r0.x = acc[mt][nt][0] * s0 + h0;
            r0.y = acc[mt][nt][1] * s1 + h1;
            r1.x = acc[mt][nt][2] * s0 + h0;
            r1.y = acc[mt][nt][3] * s1 + h1;
            *reinterpret_cast<float2*>(&Y[(size_t)row * N + col]) = r0;
            *reinterpret_cast<float2*>(&Y[(size_t)(row + 8) * N + col]) = r1;
        }
    }
}

// ---------------- fused attention (f16 tensor-core PV + ldmatrix, QT=28) ----------------
// grid: (7, 8, 64)  block: 256.  Each block: 28 query rows of one (b,h).
#define QT 28
#define SPH 792             // half pitch for S; 1584B row stride -> LDSM banks 12r, distinct
#define VTILE 112
#define VP 72               // half pitch for V; 144B row stride -> LDSM banks 4k, distinct
#define ATTN_SMEM ((QT*KD + NKEY + 32)*4 + (32*SPH + VTILE*VP)*2)

__global__ void __launch_bounds__(256)
attn_kernel(const float* __restrict__ attn_bias) {
    const int qt = blockIdx.x, h = blockIdx.y, b = blockIdx.z;
    extern __shared__ char smraw[];
    float*  sQ    = (float*)smraw;                              // QT*16 = 448 f
    float*  sBias = sQ + QT*KD;                                 // 784 f
    float*  sInv  = sBias + NKEY;                               // 32 f
    __half* sS    = (__half*)(smraw + (QT*KD + NKEY + 32)*4);   // 32*SPH h
    __half* sV    = sS + 32*SPH;                                // VTILE*VP h
    const int tid = threadIdx.x;
    const int q0 = qt * QT;

    // stage Q, bias; zero S pad rows 28..31
    for (int i = tid; i < QT*KD; i += 256) {
        int q = i / KD, t = i % KD;
        sQ[i] = g_q[((size_t)(b*NQ) + q0 + q) * (NH*KD) + h*KD + t];
    }
    for (int i = tid; i < NKEY; i += 256) sBias[i] = attn_bias[h*NKEY + i];
    for (int i = tid; i < 4*SPH; i += 256) sS[28*SPH + i] = __ushort_as_half(0);
    __syncthreads();

    // phase 1: S[q][j] = 0.25 * q.k + bias  -> f16
    for (int j = tid; j < NKEY; j += 256) {
        float kr[KD];
        const float4* kp = reinterpret_cast<const float4*>(
            g_k + ((size_t)(b*NKEY) + j) * (NH*KD) + h*KD);
#pragma unroll
        for (int t = 0; t < 4; t++) {
            float4 v = kp[t];
            kr[t*4+0] = v.x; kr[t*4+1] = v.y; kr[t*4+2] = v.z; kr[t*4+3] = v.w;
        }
        const int jx = j % RES, jy = j / RES;
#pragma unroll 2
        for (int q = 0; q < QT; q++) {
            const int qg = q0 + q;
            const int qx = 2*(qg % RES2), qy = 2*(qg / RES2);
            float s = 0.f;
#pragma unroll
            for (int t = 0; t < KD; t++) s += sQ[q*KD + t] * kr[t];
            const int dxa = qx > jx ? qx - jx : jx - qx;
            const int dya = qy > jy ? qy - jy : jy - qy;
            sS[q*SPH + j] = __float2half(s * 0.25f + sBias[dxa*RES + dya]);
        }
    }
    __syncthreads();

    // phase 2: row softmax; store exp as f16, sum the rounded values
    const int warp = tid >> 5, lane = tid & 31;
    for (int r = warp; r < QT; r += 8) {
        float m = -1e30f;
        for (int j = lane; j < NKEY; j += 32) m = fmaxf(m, __half2float(sS[r*SPH + j]));
#pragma unroll
        for (int o = 16; o > 0; o >>= 1) m = fmaxf(m, __shfl_xor_sync(0xffffffffu, m, o));
        float sum = 0.f;
        for (int j = lane; j < NKEY; j += 32) {
            float e = __expf(__half2float(sS[r*SPH + j]) - m);
            __half he = __float2half(e);
            sS[r*SPH + j] = he;
            sum += __half2float(he);
        }
#pragma unroll
        for (int o = 16; o > 0; o >>= 1) sum += __shfl_xor_sync(0xffffffffu, sum, o);
        if (lane == 0) sInv[r] = 1.f / sum;
    }
    __syncthreads();

    // phase 3: O[32,64] = P[32,784] @ V[784,64] via mma.m16n8k16 + ldmatrix
    // warp w owns output columns [w*8, w*8+8)
    const int grp = lane >> 2, t4 = lane & 3;
    const int l16 = lane & 15, lhi8 = (lane >> 4) * 8;
    float c[2][4] = {{0.f,0.f,0.f,0.f},{0.f,0.f,0.f,0.f}};

    for (int kt = 0; kt < NKEY; kt += VTILE) {
        // stage V tile as f16 [k][col], pitch VP
#pragma unroll
        for (int it = 0; it < 7; it++) {
            int i = tid + it * 256;
            int j = i >> 4, d4 = i & 15;
            float4 v = *reinterpret_cast<const float4*>(
                &g_v[((size_t)(b*NKEY) + kt + j) * DH + h*DV + d4*4]);
            uint2 u;
            u.x = h2u(__floats2half2_rn(v.x, v.y));
            u.y = h2u(__floats2half2_rn(v.z, v.w));
            *reinterpret_cast<uint2*>(&sV[j*VP + d4*4]) = u;
        }
        __syncthreads();

#pragma unroll
        for (int ks = 0; ks < VTILE; ks += 16) {
            const int kg = kt + ks;
            uint32_t b0, b1;
            ldsm_x2t(b0, b1, smaddr(&sV[(ks + l16) * VP + warp*8]));
#pragma unroll
            for (int mt = 0; mt < 2; mt++) {
                uint32_t a0, a1, a2, a3;
                ldsm_x4(a0, a1, a2, a3,
                        smaddr(&sS[(mt*16 + l16) * SPH + kg + lhi8]));
                asm volatile(
                    "mma.sync.aligned.m16n8k16.row.col.f32.f16.f16.f32 "
                    "{%0,%1,%2,%3}, {%4,%5,%6,%7}, {%8,%9}, {%0,%1,%2,%3};\n"
                    : "+f"(c[mt][0]), "+f"(c[mt][1]), "+f"(c[mt][2]), "+f"(c[mt][3])
                    : "r"(a0), "r"(a1), "r"(a2), "r"(a3), "r"(b0), "r"(b1));
            }
        }
        __syncthreads();
    }

    // epilogue: c[mt][0,1] -> row mt*16+grp ; c[mt][2,3] -> row mt*16+8+grp
    {
        const int ocol = warp*8 + 2*t4;
#pragma unroll
        for (int mt = 0; mt < 2; mt++) {
            int r0 = mt*16 + grp;
            size_t o0 = ((size_t)(b*NQ) + q0 + r0) * DH + h*DV + ocol;
            float inv0 = sInv[r0];
            g_ao[o0]     = c[mt][0] * inv0 + g_vloc[o0];
            g_ao[o0 + 1] = c[mt][1] * inv0 + g_vloc[o0 + 1];
            int r1 = mt*16 + 8 + grp;
            if (r1 < QT) {
                size_t o1 = ((size_t)(b*NQ) + q0 + r1) * DH + h*DV + ocol;
                float inv1 = sInv[r1];
                g_ao[o1]     = c[mt][2] * inv1 + g_vloc[o1];
                g_ao[o1 + 1] = c[mt][3] * inv1 + g_vloc[o1 + 1];
            }
        }
    }
}

// ---------------- launch ----------------
extern "C" void kernel_launch(void* const* d_in, const int* in_sizes, int n_in,
                              void* d_out, int out_size) {
    const float* x         = (const float*)d_in[0];
    const float* q_local_w = (const float*)d_in[1];
    const float* q_local_b = (const float*)d_in[2];
    const float* q_proj_w  = (const float*)d_in[3];
    const float* q_proj_b  = (const float*)d_in[4];
    const float* q_bn_s    = (const float*)d_in[5];
    const float* q_bn_b    = (const float*)d_in[6];
    const float* k_w       = (const float*)d_in[7];
    const float* k_b       = (const float*)d_in[8];
    const float* k_bn_s    = (const float*)d_in[9];
    const float* k_bn_b    = (const float*)d_in[10];
    const float* v_w       = (const float*)d_in[11];
    const float* v_b       = (const float*)d_in[12];
    const float* v_bn_s    = (const float*)d_in[13];
    const float* v_bn_b    = (const float*)d_in[14];
    const float* vloc_w    = (const float*)d_in[15];
    const float* vloc_b    = (const float*)d_in[16];
    const float* vloc_bn_s = (const float*)d_in[17];
    const float* vloc_bn_b = (const float*)d_in[18];
    const float* proj_w    = (const float*)d_in[19];
    const float* proj_b    = (const float*)d_in[20];
    const float* proj_bn_s = (const float*)d_in[21];
    const float* proj_bn_b = (const float*)d_in[22];
    const float* attn_bias = (const float*)d_in[23];
    float* out = (float*)d_out;

    float *p_qds, *p_q, *p_k, *p_v, *p_ao;
    cudaGetSymbolAddress((void**)&p_qds, g_qds);
    cudaGetSymbolAddress((void**)&p_q,   g_q);
    cudaGetSymbolAddress((void**)&p_k,   g_k);
    cudaGetSymbolAddress((void**)&p_v,   g_v);
    cudaGetSymbolAddress((void**)&p_ao,  g_ao);

    // 1. q local conv + subsample residual -> g_qds
    {
        int total = BATCH * NQ * CIN;
        conv_q_kernel<<<(total + 255)/256, 256>>>(x, q_local_w, q_local_b);
    }
    // 2. q projection
    {
        dim3 grid((NH*KD)/GBN, MQ/GBM);
        gemm_f16_kernel<<<grid, 256>>>(p_qds, q_proj_w, q_proj_b, q_bn_s, q_bn_b, p_q,
                                       MQ, NH*KD, CIN);
    }
    // 3. k
    {
        dim3 grid((NH*KD)/GBN, MK/GBM);
        gemm_f16_kernel<<<grid, 256>>>(x, k_w, k_b, k_bn_s, k_bn_b, p_k,
                                       MK, NH*KD, CIN);
    }
    // 4. v
    {
        dim3 grid(DH/GBN, MK/GBM);
        gemm_f16_kernel<<<grid, 256>>>(x, v_w, v_b, v_bn_s, v_bn_b, p_v,
                                       MK, DH, CIN);
    }
    // 5. v_local conv
    {
        int total = BATCH * NQ * DH;
        conv_vloc_kernel<<<(total + 255)/256, 256>>>(vloc_w, vloc_b, vloc_bn_s, vloc_bn_b);
    }
    // 6. attention (+v_local)
    {
        cudaFuncSetAttribute(attn_kernel, cudaFuncAttributeMaxDynamicSharedMemorySize, ATTN_SMEM);
        dim3 grid(NQ/QT, NH, BATCH);
        attn_kernel<<<grid, 256, ATTN_SMEM>>>(attn_bias);
    }
    // 7. projection
    {
        dim3 grid(COUT/GBN, MQ/GBM);
        gemm_f16_kernel<<<grid, 256>>>(p_ao, proj_w, proj_b, proj_bn_s, proj_bn_b, out,
                                       MQ, COUT, DH);
    }
}

// round 14
// speedup vs baseline: 4.8288x; 1.0801x over previous
#include <cuda_runtime.h>
#include <cuda_fp16.h>
#include <cuda_bf16.h>
#include <cstdint>

// ---------------- problem constants ----------------
#define BATCH 64
#define RES 28
#define RES2 14
#define NH 8
#define KD 16
#define DV 64
#define DH 512
#define CIN 384
#define COUT 768
#define NKEY (RES*RES)      // 784
#define NQ (RES2*RES2)      // 196
#define MQ (BATCH*NQ)       // 12544
#define MK (BATCH*NKEY)     // 50176

// ---------------- device scratch ----------------
__device__ __half g_xh  [(size_t)MK * CIN];     // x as f16
__device__ __half g_qdsh[(size_t)MQ * CIN];     // q local branch, f16
__device__ __half g_aoh [(size_t)MQ * DH];      // attn out (+vloc), f16
__device__ __half g_wqh [CIN * 128];            // q_proj_w f16 [k][n]
__device__ __half g_wkh [CIN * 128];            // k_w f16
__device__ __half g_wvh [CIN * DH];             // v_w f16
__device__ __half g_wph [DH * COUT];            // proj_w f16
__device__ float  g_q   [(size_t)MQ * (NH*KD)];
__device__ float  g_k   [(size_t)MK * (NH*KD)];
__device__ float  g_v   [(size_t)MK * DH];
__device__ float  g_vloc[(size_t)MQ * DH];

__device__ __forceinline__ uint32_t h2u(__half2 h) {
    return *reinterpret_cast<uint32_t*>(&h);
}
__device__ __forceinline__ uint32_t smaddr(const void* p) {
    return (uint32_t)__cvta_generic_to_shared(p);
}
__device__ __forceinline__ void ldsm_x4(uint32_t& r0, uint32_t& r1, uint32_t& r2, uint32_t& r3, uint32_t a) {
    asm volatile("ldmatrix.sync.aligned.m8n8.x4.shared.b16 {%0,%1,%2,%3}, [%4];"
                 : "=r"(r0), "=r"(r1), "=r"(r2), "=r"(r3) : "r"(a));
}
__device__ __forceinline__ void ldsm_x4t(uint32_t& r0, uint32_t& r1, uint32_t& r2, uint32_t& r3, uint32_t a) {
    asm volatile("ldmatrix.sync.aligned.m8n8.x4.trans.shared.b16 {%0,%1,%2,%3}, [%4];"
                 : "=r"(r0), "=r"(r1), "=r"(r2), "=r"(r3) : "r"(a));
}
__device__ __forceinline__ void ldsm_x2t(uint32_t& r0, uint32_t& r1, uint32_t a) {
    asm volatile("ldmatrix.sync.aligned.m8n8.x2.trans.shared.b16 {%0,%1}, [%2];"
                 : "=r"(r0), "=r"(r1) : "r"(a));
}
#define CP_ASYNC16(dst, src) \
    asm volatile("cp.async.cg.shared.global [%0], [%1], 16;" :: "r"(dst), "l"(src))
#define CP_COMMIT() asm volatile("cp.async.commit_group;" ::: "memory")
#define CP_WAIT(n)  asm volatile("cp.async.wait_group %0;" :: "n"(n) : "memory")

// ---------------- prep: f32 -> f16 elementwise (n % 4 == 0) ----------------
__global__ void cvt_f16_kernel(const float* __restrict__ in, __half* __restrict__ out, int n4) {
    int i = blockIdx.x * blockDim.x + threadIdx.x;
    if (i >= n4) return;
    float4 v = reinterpret_cast<const float4*>(in)[i];
    uint2 u;
    u.x = h2u(__floats2half2_rn(v.x, v.y));
    u.y = h2u(__floats2half2_rn(v.z, v.w));
    reinterpret_cast<uint2*>(out)[i] = u;
}

// ---------------- depthwise 3x3 stride-2 SAME conv + residual subsample (q) ----
__global__ void conv_q_kernel(const float* __restrict__ x,
                              const float* __restrict__ w,
                              const float* __restrict__ bias) {
    int idx = blockIdx.x * blockDim.x + threadIdx.x;
    const int total = BATCH * NQ * CIN;
    if (idx >= total) return;
    int c  = idx % CIN;
    int p  = idx / CIN;
    int b  = p / NQ;
    int pp = p % NQ;
    int oy = pp / RES2, ox = pp % RES2;
    float acc = bias[c];
#pragma unroll
    for (int dy = 0; dy < 3; dy++) {
        int iy = 2*oy + dy;
        if (iy >= RES) continue;
#pragma unroll
        for (int dx = 0; dx < 3; dx++) {
            int ix = 2*ox + dx;
            if (ix >= RES) continue;
            acc += x[(((size_t)b*RES + iy)*RES + ix)*CIN + c] * w[(dy*3+dx)*CIN + c];
        }
    }
    acc += x[(((size_t)b*RES + 2*oy)*RES + 2*ox)*CIN + c];
    g_qdsh[idx] = __float2half(acc);
}

// ---------------- depthwise 3x3 stride-2 SAME conv + BN (v_local) ----------
__global__ void conv_vloc_kernel(const float* __restrict__ w,
                                 const float* __restrict__ bias,
                                 const float* __restrict__ bns,
                                 const float* __restrict__ bnb) {
    int idx = blockIdx.x * blockDim.x + threadIdx.x;
    const int total = BATCH * NQ * DH;
    if (idx >= total) return;
    int c  = idx % DH;
    int p  = idx / DH;
    int b  = p / NQ;
    int pp = p % NQ;
    int oy = pp / RES2, ox = pp % RES2;
    float acc = bias[c];
#pragma unroll
    for (int dy = 0; dy < 3; dy++) {
        int iy = 2*oy + dy;
        if (iy >= RES) continue;
#pragma unroll
        for (int dx = 0; dx < 3; dx++) {
            int ix = 2*ox + dx;
            if (ix >= RES) continue;
            acc += g_v[(((size_t)b*RES + iy)*RES + ix)*DH + c] * w[(dy*3+dx)*DH + c];
        }
    }
    g_vloc[idx] = acc * bns[c] + bnb[c];
}

// ---------------- f16 GEMM: m16n8k16 + ldmatrix + cp.async 3-stage ----------
// Y[m,n] = (sum_k A[m,k]*W[k,n] + bias[n]) * s[n] + b2[n]
// A f16 [M][K], W f16 [K][N].  M%128==0, N%128==0, K%32==0.
#define GBM 128
#define GBN 128
#define GBK 32
#define STAGES 3
#define APITCH 24       // halves per A row within a k16 sub-tile; 48B stride
#define BPH 136         // halves per B k-row; 272B stride
#define A_STAGE_H (2 * GBM * APITCH)       // 6144 halves = 12288 B
#define B_STAGE_H (GBK * BPH)              // 4352 halves = 8704 B
#define GEMM_SMEM ((A_STAGE_H + B_STAGE_H) * STAGES * 2)   // 62976 B

__global__ void __launch_bounds__(256, 2)
gemm_f16_kernel(const __half* __restrict__ A, const __half* __restrict__ W,
                const float* __restrict__ bias, const float* __restrict__ bns,
                const float* __restrict__ bnb, float* __restrict__ Y,
                int M, int N, int K) {
    extern __shared__ __half sh[];
    __half* As = sh;                         // STAGES x A_STAGE_H
    __half* Bs = sh + STAGES * A_STAGE_H;    // STAGES x B_STAGE_H
    const int bm = blockIdx.y * GBM, bn = blockIdx.x * GBN;
    const int tid = threadIdx.x;
    const int warp = tid >> 5, lane = tid & 31;
    const int grp = lane >> 2, t4 = lane & 3;
    const int wm = (warp & 3) * 32;
    const int wn = (warp >> 2) * 64;
    const int l16 = lane & 15, lhi8 = (lane >> 4) * 8;

    // cp.async chunk geometry (2 chunks each for A and B per thread per stage)
    // A chunk i: row=i>>2, kc=(i>>1)&1, kh=(i&1)*8
    // B chunk i: krow=i>>4, nc=i&15
    const uint32_t aBase = smaddr(As), bBase = smaddr(Bs);

    float acc[2][8][4];
#pragma unroll
    for (int i = 0; i < 2; i++)
#pragma unroll
        for (int j = 0; j < 8; j++)
#pragma unroll
            for (int c = 0; c < 4; c++) acc[i][j][c] = 0.f;

    const int nk = K / GBK;

    auto issue_stage = [&](int ki) {
        const int st = ki % STAGES;
        const int k0 = ki * GBK;
        const uint32_t ad = aBase + st * A_STAGE_H * 2;
        const uint32_t bd = bBase + st * B_STAGE_H * 2;
#pragma unroll
        for (int p = 0; p < 2; p++) {
            int i = tid + p * 256;
            int row = i >> 2, kc = (i >> 1) & 1, kh = (i & 1) * 8;
            CP_ASYNC16(ad + (kc * GBM * APITCH + row * APITCH + kh) * 2,
                       &A[(size_t)(bm + row) * K + k0 + kc * 16 + kh]);
        }
#pragma unroll
        for (int p = 0; p < 2; p++) {
            int i = tid + p * 256;
            int krow = i >> 4, nc = i & 15;
            CP_ASYNC16(bd + (krow * BPH + nc * 8) * 2,
                       &W[(size_t)(k0 + krow) * N + bn + nc * 8]);
        }
    };

    // prologue: stages 0,1
    issue_stage(0); CP_COMMIT();
    issue_stage(1); CP_COMMIT();

    for (int ki = 0; ki < nk; ki++) {
        if (ki + 2 < nk) issue_stage(ki + 2);
        CP_COMMIT();          // one group per iter (possibly empty)
        CP_WAIT(2);           // stage ki's group complete (this thread)
        __syncthreads();      // all threads' chunks visible

        const int st = ki % STAGES;
        const __half* pA = As + st * A_STAGE_H;
        const __half* pB = Bs + st * B_STAGE_H;
#pragma unroll
        for (int kc = 0; kc < 2; kc++) {
            uint32_t af[2][4];
#pragma unroll
            for (int mt = 0; mt < 2; mt++)
                ldsm_x4(af[mt][0], af[mt][1], af[mt][2], af[mt][3],
                        smaddr(&pA[kc * GBM * APITCH + (wm + mt*16 + l16) * APITCH + lhi8]));
            uint32_t bf[8][2];
#pragma unroll
            for (int nt2 = 0; nt2 < 4; nt2++) {
                uint32_t q0, q1, q2, q3;
                ldsm_x4t(q0, q1, q2, q3,
                         smaddr(&pB[(kc*16 + l16) * BPH + wn + nt2*16 + lhi8]));
                bf[2*nt2    ][0] = q0; bf[2*nt2    ][1] = q1;
                bf[2*nt2 + 1][0] = q2; bf[2*nt2 + 1][1] = q3;
            }
#pragma unroll
            for (int mt = 0; mt < 2; mt++)
#pragma unroll
                for (int nt = 0; nt < 8; nt++) {
                    asm volatile(
                        "mma.sync.aligned.m16n8k16.row.col.f32.f16.f16.f32 "
                        "{%0,%1,%2,%3}, {%4,%5,%6,%7}, {%8,%9}, {%0,%1,%2,%3};\n"
                        : "+f"(acc[mt][nt][0]), "+f"(acc[mt][nt][1]),
                          "+f"(acc[mt][nt][2]), "+f"(acc[mt][nt][3])
                        : "r"(af[mt][0]), "r"(af[mt][1]), "r"(af[mt][2]), "r"(af[mt][3]),
                          "r"(bf[nt][0]), "r"(bf[nt][1]));
                }
        }
        __syncthreads();      // protect stage (ki+1)%STAGES... and reuse of st by issue at ki+? (st reissued at ki+STAGES)
    }

    // epilogue: (acc + bias)*s + b2  ==  acc*s + (bias*s + b2)
#pragma unroll
    for (int nt = 0; nt < 8; nt++) {
        int col = bn + wn + nt * 8 + t4 * 2;
        float s0 = bns[col],     s1 = bns[col + 1];
        float h0 = bias[col] * s0 + bnb[col];
        float h1 = bias[col + 1] * s1 + bnb[col + 1];
#pragma unroll
        for (int mt = 0; mt < 2; mt++) {
            int row = bm + wm + mt * 16 + grp;
            float2 r0, r1;
            r0.x = acc[mt][nt][0] * s0 + h0;
            r0.y = acc[mt][nt][1] * s1 + h1;
            r1.x = acc[mt][nt][2] * s0 + h0;
            r1.y = acc[mt][nt][3] * s1 + h1;
            *reinterpret_cast<float2*>(&Y[(size_t)row * N + col]) = r0;
            *reinterpret_cast<float2*>(&Y[(size_t)(row + 8) * N + col]) = r1;
        }
    }
}

// ---------------- fused attention (f16 tensor-core PV + ldmatrix, QT=28) ----------------
#define QT 28
#define SPH 792             // half pitch for S; 1584B row stride
#define VTILE 112
#define VP 72               // half pitch for V; 144B row stride
#define ATTN_SMEM ((QT*KD + NKEY + 32)*4 + (32*SPH + VTILE*VP)*2)

__global__ void __launch_bounds__(256)
attn_kernel(const float* __restrict__ attn_bias) {
    const int qt = blockIdx.x, h = blockIdx.y, b = blockIdx.z;
    extern __shared__ char smraw[];
    float*  sQ    = (float*)smraw;
    float*  sBias = sQ + QT*KD;
    float*  sInv  = sBias + NKEY;
    __half* sS    = (__half*)(smraw + (QT*KD + NKEY + 32)*4);
    __half* sV    = sS + 32*SPH;
    const int tid = threadIdx.x;
    const int q0 = qt * QT;

    for (int i = tid; i < QT*KD; i += 256) {
        int q = i / KD, t = i % KD;
        sQ[i] = g_q[((size_t)(b*NQ) + q0 + q) * (NH*KD) + h*KD + t];
    }
    for (int i = tid; i < NKEY; i += 256) sBias[i] = attn_bias[h*NKEY + i];
    for (int i = tid; i < 4*SPH; i += 256) sS[28*SPH + i] = __ushort_as_half(0);
    __syncthreads();

    // phase 1: S = 0.25 * q.k + bias -> f16
    for (int j = tid; j < NKEY; j += 256) {
        float kr[KD];
        const float4* kp = reinterpret_cast<const float4*>(
            g_k + ((size_t)(b*NKEY) + j) * (NH*KD) + h*KD);
#pragma unroll
        for (int t = 0; t < 4; t++) {
            float4 v = kp[t];
            kr[t*4+0] = v.x; kr[t*4+1] = v.y; kr[t*4+2] = v.z; kr[t*4+3] = v.w;
        }
        const int jx = j % RES, jy = j / RES;
#pragma unroll 2
        for (int q = 0; q < QT; q++) {
            const int qg = q0 + q;
            const int qx = 2*(qg % RES2), qy = 2*(qg / RES2);
            float s = 0.f;
#pragma unroll
            for (int t = 0; t < KD; t++) s += sQ[q*KD + t] * kr[t];
            const int dxa = qx > jx ? qx - jx : jx - qx;
            const int dya = qy > jy ? qy - jy : jy - qy;
            sS[q*SPH + j] = __float2half(s * 0.25f + sBias[dxa*RES + dya]);
        }
    }
    __syncthreads();

    // phase 2: softmax
    const int warp = tid >> 5, lane = tid & 31;
    for (int r = warp; r < QT; r += 8) {
        float m = -1e30f;
        for (int j = lane; j < NKEY; j += 32) m = fmaxf(m, __half2float(sS[r*SPH + j]));
#pragma unroll
        for (int o = 16; o > 0; o >>= 1) m = fmaxf(m, __shfl_xor_sync(0xffffffffu, m, o));
        float sum = 0.f;
        for (int j = lane; j < NKEY; j += 32) {
            float e = __expf(__half2float(sS[r*SPH + j]) - m);
            __half he = __float2half(e);
            sS[r*SPH + j] = he;
            sum += __half2float(he);
        }
#pragma unroll
        for (int o = 16; o > 0; o >>= 1) sum += __shfl_xor_sync(0xffffffffu, sum, o);
        if (lane == 0) sInv[r] = 1.f / sum;
    }
    __syncthreads();

    // phase 3: O = P @ V via mma.m16n8k16 + ldmatrix
    const int grp = lane >> 2, t4 = lane & 3;
    const int l16 = lane & 15, lhi8 = (lane >> 4) * 8;
    float c[2][4] = {{0.f,0.f,0.f,0.f},{0.f,0.f,0.f,0.f}};

    for (int kt = 0; kt < NKEY; kt += VTILE) {
#pragma unroll
        for (int it = 0; it < 7; it++) {
            int i = tid + it * 256;
            int j = i >> 4, d4 = i & 15;
            float4 v = *reinterpret_cast<const float4*>(
                &g_v[((size_t)(b*NKEY) + kt + j) * DH + h*DV + d4*4]);
            uint2 u;
            u.x = h2u(__floats2half2_rn(v.x, v.y));
            u.y = h2u(__floats2half2_rn(v.z, v.w));
            *reinterpret_cast<uint2*>(&sV[j*VP + d4*4]) = u;
        }
        __syncthreads();

#pragma unroll
        for (int ks = 0; ks < VTILE; ks += 16) {
            const int kg = kt + ks;
            uint32_t b0, b1;
            ldsm_x2t(b0, b1, smaddr(&sV[(ks + l16) * VP + warp*8]));
#pragma unroll
            for (int mt = 0; mt < 2; mt++) {
                uint32_t a0, a1, a2, a3;
                ldsm_x4(a0, a1, a2, a3,
                        smaddr(&sS[(mt*16 + l16) * SPH + kg + lhi8]));
                asm volatile(
                    "mma.sync.aligned.m16n8k16.row.col.f32.f16.f16.f32 "
                    "{%0,%1,%2,%3}, {%4,%5,%6,%7}, {%8,%9}, {%0,%1,%2,%3};\n"
                    : "+f"(c[mt][0]), "+f"(c[mt][1]), "+f"(c[mt][2]), "+f"(c[mt][3])
                    : "r"(a0), "r"(a1), "r"(a2), "r"(a3), "r"(b0), "r"(b1));
            }
        }
        __syncthreads();
    }

    // epilogue -> f16 (+ v_local)
    {
        const int ocol = warp*8 + 2*t4;
#pragma unroll
        for (int mt = 0; mt < 2; mt++) {
            int r0 = mt*16 + grp;
            size_t o0 = ((size_t)(b*NQ) + q0 + r0) * DH + h*DV + ocol;
            float inv0 = sInv[r0];
            g_aoh[o0]     = __float2half(c[mt][0] * inv0 + g_vloc[o0]);
            g_aoh[o0 + 1] = __float2half(c[mt][1] * inv0 + g_vloc[o0 + 1]);
            int r1 = mt*16 + 8 + grp;
            if (r1 < QT) {
                size_t o1 = ((size_t)(b*NQ) + q0 + r1) * DH + h*DV + ocol;
                float inv1 = sInv[r1];
                g_aoh[o1]     = __float2half(c[mt][2] * inv1 + g_vloc[o1]);
                g_aoh[o1 + 1] = __float2half(c[mt][3] * inv1 + g_vloc[o1 + 1]);
            }
        }
    }
}

// ---------------- launch ----------------
extern "C" void kernel_launch(void* const* d_in, const int* in_sizes, int n_in,
                              void* d_out, int out_size) {
    const float* x         = (const float*)d_in[0];
    const float* q_local_w = (const float*)d_in[1];
    const float* q_local_b = (const float*)d_in[2];
    const float* q_proj_w  = (const float*)d_in[3];
    const float* q_proj_b  = (const float*)d_in[4];
    const float* q_bn_s    = (const float*)d_in[5];
    const float* q_bn_b    = (const float*)d_in[6];
    const float* k_w       = (const float*)d_in[7];
    const float* k_b       = (const float*)d_in[8];
    const float* k_bn_s    = (const float*)d_in[9];
    const float* k_bn_b    = (const float*)d_in[10];
    const float* v_w       = (const float*)d_in[11];
    const float* v_b       = (const float*)d_in[12];
    const float* v_bn_s    = (const float*)d_in[13];
    const float* v_bn_b    = (const float*)d_in[14];
    const float* vloc_w    = (const float*)d_in[15];
    const float* vloc_b    = (const float*)d_in[16];
    const float* vloc_bn_s = (const float*)d_in[17];
    const float* vloc_bn_b = (const float*)d_in[18];
    const float* proj_w    = (const float*)d_in[19];
    const float* proj_b    = (const float*)d_in[20];
    const float* proj_bn_s = (const float*)d_in[21];
    const float* proj_bn_b = (const float*)d_in[22];
    const float* attn_bias = (const float*)d_in[23];
    float* out = (float*)d_out;

    __half *p_xh, *p_qdsh, *p_aoh, *p_wqh, *p_wkh, *p_wvh, *p_wph;
    float  *p_q, *p_k, *p_v;
    cudaGetSymbolAddress((void**)&p_xh,   g_xh);
    cudaGetSymbolAddress((void**)&p_qdsh, g_qdsh);
    cudaGetSymbolAddress((void**)&p_aoh,  g_aoh);
    cudaGetSymbolAddress((void**)&p_wqh,  g_wqh);
    cudaGetSymbolAddress((void**)&p_wkh,  g_wkh);
    cudaGetSymbolAddress((void**)&p_wvh,  g_wvh);
    cudaGetSymbolAddress((void**)&p_wph,  g_wph);
    cudaGetSymbolAddress((void**)&p_q,    g_q);
    cudaGetSymbolAddress((void**)&p_k,    g_k);
    cudaGetSymbolAddress((void**)&p_v,    g_v);

    cudaFuncSetAttribute(gemm_f16_kernel, cudaFuncAttributeMaxDynamicSharedMemorySize, GEMM_SMEM);
    cudaFuncSetAttribute(attn_kernel,     cudaFuncAttributeMaxDynamicSharedMemorySize, ATTN_SMEM);

    // prep: f16 conversions
    {
        int n4 = MK * CIN / 4;
        cvt_f16_kernel<<<(n4 + 255)/256, 256>>>(x, p_xh, n4);
        cvt_f16_kernel<<<(CIN*128/4 + 255)/256, 256>>>(q_proj_w, p_wqh, CIN*128/4);
        cvt_f16_kernel<<<(CIN*128/4 + 255)/256, 256>>>(k_w,      p_wkh, CIN*128/4);
        cvt_f16_kernel<<<(CIN*DH/4  + 255)/256, 256>>>(v_w,      p_wvh, CIN*DH/4);
        cvt_f16_kernel<<<(DH*COUT/4 + 255)/256, 256>>>(proj_w,   p_wph, DH*COUT/4);
    }
    // 1. q local conv -> g_qdsh (f16)
    {
        int total = BATCH * NQ * CIN;
        conv_q_kernel<<<(total + 255)/256, 256>>>(x, q_local_w, q_local_b);
    }
    // 2. q projection
    gemm_f16_kernel<<<dim3(1, MQ/GBM), 256, GEMM_SMEM>>>(p_qdsh, p_wqh, q_proj_b, q_bn_s, q_bn_b, p_q, MQ, 128, CIN);
    // 3. k
    gemm_f16_kernel<<<dim3(1, MK/GBM), 256, GEMM_SMEM>>>(p_xh, p_wkh, k_b, k_bn_s, k_bn_b, p_k, MK, 128, CIN);
    // 4. v
    gemm_f16_kernel<<<dim3(DH/GBN, MK/GBM), 256, GEMM_SMEM>>>(p_xh, p_wvh, v_b, v_bn_s, v_bn_b, p_v, MK, DH, CIN);
    // 5. v_local conv
    {
        int total = BATCH * NQ * DH;
        conv_vloc_kernel<<<(total + 255)/256, 256>>>(vloc_w, vloc_b, vloc_bn_s, vloc_bn_b);
    }
    // 6. attention (+v_local) -> g_aoh (f16)
    attn_kernel<<<dim3(NQ/QT, NH, BATCH), 256, ATTN_SMEM>>>(attn_bias);
    // 7. projection
    gemm_f16_kernel<<<dim3(COUT/GBN, MQ/GBM), 256, GEMM_SMEM>>>(p_aoh, p_wph, proj_b, proj_bn_s, proj_bn_b, out, MQ, COUT, DH);
}

// round 17
// speedup vs baseline: 5.0786x; 1.0517x over previous
#include <cuda_runtime.h>
#include <cuda_fp16.h>
#include <cuda_bf16.h>
#include <cstdint>

// ---------------- problem constants ----------------
#define BATCH 64
#define RES 28
#define RES2 14
#define NH 8
#define KD 16
#define DV 64
#define DH 512
#define CIN 384
#define COUT 768
#define NKEY (RES*RES)      // 784
#define NQ (RES2*RES2)      // 196
#define MQ (BATCH*NQ)       // 12544
#define MK (BATCH*NKEY)     // 50176

// ---------------- device scratch ----------------
__device__ __half g_xh  [(size_t)MK * CIN];     // x as f16
__device__ __half g_qdsh[(size_t)MQ * CIN];     // q local branch, f16
__device__ __half g_aoh [(size_t)MQ * DH];      // attn out (+vloc), f16
__device__ __half g_wqh [CIN * 128];            // q_proj_w f16 [k][n]
__device__ __half g_wkh [CIN * 128];            // k_w f16
__device__ __half g_wvh [CIN * DH];             // v_w f16
__device__ __half g_wph [DH * COUT];            // proj_w f16
__device__ __half g_qh  [(size_t)MQ * (NH*KD)]; // q f16
__device__ float  g_k   [(size_t)MK * (NH*KD)]; // k f32 (score precision)
__device__ __half g_vh  [(size_t)MK * DH];      // v f16
__device__ float  g_vloc[(size_t)MQ * DH];

__device__ __forceinline__ uint32_t h2u(__half2 h) {
    return *reinterpret_cast<uint32_t*>(&h);
}
__device__ __forceinline__ uint32_t smaddr(const void* p) {
    return (uint32_t)__cvta_generic_to_shared(p);
}
__device__ __forceinline__ void ldsm_x4(uint32_t& r0, uint32_t& r1, uint32_t& r2, uint32_t& r3, uint32_t a) {
    asm volatile("ldmatrix.sync.aligned.m8n8.x4.shared.b16 {%0,%1,%2,%3}, [%4];"
                 : "=r"(r0), "=r"(r1), "=r"(r2), "=r"(r3) : "r"(a));
}
__device__ __forceinline__ void ldsm_x4t(uint32_t& r0, uint32_t& r1, uint32_t& r2, uint32_t& r3, uint32_t a) {
    asm volatile("ldmatrix.sync.aligned.m8n8.x4.trans.shared.b16 {%0,%1,%2,%3}, [%4];"
                 : "=r"(r0), "=r"(r1), "=r"(r2), "=r"(r3) : "r"(a));
}
__device__ __forceinline__ void ldsm_x2t(uint32_t& r0, uint32_t& r1, uint32_t a) {
    asm volatile("ldmatrix.sync.aligned.m8n8.x2.trans.shared.b16 {%0,%1}, [%2];"
                 : "=r"(r0), "=r"(r1) : "r"(a));
}
#define CP_ASYNC16(dst, src) \
    asm volatile("cp.async.cg.shared.global [%0], [%1], 16;" :: "r"(dst), "l"(src))
#define CP_COMMIT() asm volatile("cp.async.commit_group;" ::: "memory")
#define CP_WAIT(n)  asm volatile("cp.async.wait_group %0;" :: "n"(n) : "memory")

// ---------------- prep: f32 -> f16 elementwise (n % 4 == 0) ----------------
__global__ void cvt_f16_kernel(const float* __restrict__ in, __half* __restrict__ out, int n4) {
    int i = blockIdx.x * blockDim.x + threadIdx.x;
    if (i >= n4) return;
    float4 v = reinterpret_cast<const float4*>(in)[i];
    uint2 u;
    u.x = h2u(__floats2half2_rn(v.x, v.y));
    u.y = h2u(__floats2half2_rn(v.z, v.w));
    reinterpret_cast<uint2*>(out)[i] = u;
}

// ---------------- depthwise 3x3 stride-2 SAME conv + residual subsample (q) ----
__global__ void conv_q_kernel(const float* __restrict__ x,
                              const float* __restrict__ w,
                              const float* __restrict__ bias) {
    int idx = blockIdx.x * blockDim.x + threadIdx.x;
    const int total = BATCH * NQ * CIN;
    if (idx >= total) return;
    int c  = idx % CIN;
    int p  = idx / CIN;
    int b  = p / NQ;
    int pp = p % NQ;
    int oy = pp / RES2, ox = pp % RES2;
    float acc = bias[c];
#pragma unroll
    for (int dy = 0; dy < 3; dy++) {
        int iy = 2*oy + dy;
        if (iy >= RES) continue;
#pragma unroll
        for (int dx = 0; dx < 3; dx++) {
            int ix = 2*ox + dx;
            if (ix >= RES) continue;
            acc += x[(((size_t)b*RES + iy)*RES + ix)*CIN + c] * w[(dy*3+dx)*CIN + c];
        }
    }
    acc += x[(((size_t)b*RES + 2*oy)*RES + 2*ox)*CIN + c];
    g_qdsh[idx] = __float2half(acc);
}

// ---------------- depthwise 3x3 stride-2 SAME conv + BN (v_local), f16 V in ----
__global__ void conv_vloc_kernel(const float* __restrict__ w,
                                 const float* __restrict__ bias,
                                 const float* __restrict__ bns,
                                 const float* __restrict__ bnb) {
    int idx = blockIdx.x * blockDim.x + threadIdx.x;
    const int total = BATCH * NQ * DH;
    if (idx >= total) return;
    int c  = idx % DH;
    int p  = idx / DH;
    int b  = p / NQ;
    int pp = p % NQ;
    int oy = pp / RES2, ox = pp % RES2;
    float acc = bias[c];
#pragma unroll
    for (int dy = 0; dy < 3; dy++) {
        int iy = 2*oy + dy;
        if (iy >= RES) continue;
#pragma unroll
        for (int dx = 0; dx < 3; dx++) {
            int ix = 2*ox + dx;
            if (ix >= RES) continue;
            acc += __half2float(g_vh[(((size_t)b*RES + iy)*RES + ix)*DH + c]) * w[(dy*3+dx)*DH + c];
        }
    }
    g_vloc[idx] = acc * bns[c] + bnb[c];
}

// ---------------- f16 GEMM: m16n8k16 + ldmatrix + cp.async 3-stage ----------
// Y[m,n] = (sum_k A[m,k]*W[k,n] + bias[n]) * s[n] + b2[n]; OutT in {float, __half}
// A f16 [M][K], W f16 [K][N].  M%128==0, N%128==0, K%32==0.
#define GBM 128
#define GBN 128
#define GBK 32
#define STAGES 3
#define APITCH 24       // halves per A row within a k16 sub-tile; 48B stride
#define BPH 136         // halves per B k-row; 272B stride
#define A_STAGE_H (2 * GBM * APITCH)       // 6144 halves
#define B_STAGE_H (GBK * BPH)              // 4352 halves
#define GEMM_SMEM ((A_STAGE_H + B_STAGE_H) * STAGES * 2)   // 62976 B

template <typename OutT>
__global__ void __launch_bounds__(256, 2)
gemm_f16_kernel(const __half* __restrict__ A, const __half* __restrict__ W,
                const float* __restrict__ bias, const float* __restrict__ bns,
                const float* __restrict__ bnb, OutT* __restrict__ Y,
                int M, int N, int K) {
    extern __shared__ __half sh[];
    __half* As = sh;
    __half* Bs = sh + STAGES * A_STAGE_H;
    const int bm = blockIdx.y * GBM, bn = blockIdx.x * GBN;
    const int tid = threadIdx.x;
    const int warp = tid >> 5, lane = tid & 31;
    const int grp = lane >> 2, t4 = lane & 3;
    const int wm = (warp & 3) * 32;
    const int wn = (warp >> 2) * 64;
    const int l16 = lane & 15, lhi8 = (lane >> 4) * 8;
    const uint32_t aBase = smaddr(As), bBase = smaddr(Bs);

    float acc[2][8][4];
#pragma unroll
    for (int i = 0; i < 2; i++)
#pragma unroll
        for (int j = 0; j < 8; j++)
#pragma unroll
            for (int c = 0; c < 4; c++) acc[i][j][c] = 0.f;

    const int nk = K / GBK;

    auto issue_stage = [&](int ki) {
        const int st = ki % STAGES;
        const int k0 = ki * GBK;
        const uint32_t ad = aBase + st * A_STAGE_H * 2;
        const uint32_t bd = bBase + st * B_STAGE_H * 2;
#pragma unroll
        for (int p = 0; p < 2; p++) {
            int i = tid + p * 256;
            int row = i >> 2, kc = (i >> 1) & 1, kh = (i & 1) * 8;
            CP_ASYNC16(ad + (kc * GBM * APITCH + row * APITCH + kh) * 2,
                       &A[(size_t)(bm + row) * K + k0 + kc * 16 + kh]);
        }
#pragma unroll
        for (int p = 0; p < 2; p++) {
            int i = tid + p * 256;
            int krow = i >> 4, nc = i & 15;
            CP_ASYNC16(bd + (krow * BPH + nc * 8) * 2,
                       &W[(size_t)(k0 + krow) * N + bn + nc * 8]);
        }
    };

    issue_stage(0); CP_COMMIT();
    issue_stage(1); CP_COMMIT();

    for (int ki = 0; ki < nk; ki++) {
        if (ki + 2 < nk) issue_stage(ki + 2);
        CP_COMMIT();
        CP_WAIT(2);
        __syncthreads();

        const int st = ki % STAGES;
        const __half* pA = As + st * A_STAGE_H;
        const __half* pB = Bs + st * B_STAGE_H;
#pragma unroll
        for (int kc = 0; kc < 2; kc++) {
            uint32_t af[2][4];
#pragma unroll
            for (int mt = 0; mt < 2; mt++)
                ldsm_x4(af[mt][0], af[mt][1], af[mt][2], af[mt][3],
                        smaddr(&pA[kc * GBM * APITCH + (wm + mt*16 + l16) * APITCH + lhi8]));
            uint32_t bf[8][2];
#pragma unroll
            for (int nt2 = 0; nt2 < 4; nt2++) {
                uint32_t q0, q1, q2, q3;
                ldsm_x4t(q0, q1, q2, q3,
                         smaddr(&pB[(kc*16 + l16) * BPH + wn + nt2*16 + lhi8]));
                bf[2*nt2    ][0] = q0; bf[2*nt2    ][1] = q1;
                bf[2*nt2 + 1][0] = q2; bf[2*nt2 + 1][1] = q3;
            }
#pragma unroll
            for (int mt = 0; mt < 2; mt++)
#pragma unroll
                for (int nt = 0; nt < 8; nt++) {
                    asm volatile(
                        "mma.sync.aligned.m16n8k16.row.col.f32.f16.f16.f32 "
                        "{%0,%1,%2,%3}, {%4,%5,%6,%7}, {%8,%9}, {%0,%1,%2,%3};\n"
                        : "+f"(acc[mt][nt][0]), "+f"(acc[mt][nt][1]),
                          "+f"(acc[mt][nt][2]), "+f"(acc[mt][nt][3])
                        : "r"(af[mt][0]), "r"(af[mt][1]), "r"(af[mt][2]), "r"(af[mt][3]),
                          "r"(bf[nt][0]), "r"(bf[nt][1]));
                }
        }
        __syncthreads();
    }

    // epilogue: (acc + bias)*s + b2  ==  acc*s + (bias*s + b2)
#pragma unroll
    for (int nt = 0; nt < 8; nt++) {
        int col = bn + wn + nt * 8 + t4 * 2;
        float s0 = bns[col],     s1 = bns[col + 1];
        float h0 = bias[col] * s0 + bnb[col];
        float h1 = bias[col + 1] * s1 + bnb[col + 1];
#pragma unroll
        for (int mt = 0; mt < 2; mt++) {
            int row = bm + wm + mt * 16 + grp;
            float v00 = acc[mt][nt][0] * s0 + h0;
            float v01 = acc[mt][nt][1] * s1 + h1;
            float v10 = acc[mt][nt][2] * s0 + h0;
            float v11 = acc[mt][nt][3] * s1 + h1;
            if constexpr (sizeof(OutT) == 2) {
                __half* Yh = reinterpret_cast<__half*>(Y);
                *reinterpret_cast<__half2*>(&Yh[(size_t)row * N + col])       = __floats2half2_rn(v00, v01);
                *reinterpret_cast<__half2*>(&Yh[(size_t)(row + 8) * N + col]) = __floats2half2_rn(v10, v11);
            } else {
                float* Yf = reinterpret_cast<float*>(Y);
                *reinterpret_cast<float2*>(&Yf[(size_t)row * N + col])       = make_float2(v00, v01);
                *reinterpret_cast<float2*>(&Yf[(size_t)(row + 8) * N + col]) = make_float2(v10, v11);
            }
        }
    }
}

// ---------------- fused attention (f16 tensor-core PV + ldmatrix, QT=28) ----------------
#define QT 28
#define SPH 792             // half pitch for S; 1584B row stride
#define VTILE 112
#define VP 72               // half pitch for V; 144B row stride
#define ATTN_SMEM ((QT*KD + NKEY + 32)*4 + (32*SPH + VTILE*VP)*2)

__global__ void __launch_bounds__(256)
attn_kernel(const float* __restrict__ attn_bias) {
    const int qt = blockIdx.x, h = blockIdx.y, b = blockIdx.z;
    extern __shared__ char smraw[];
    float*  sQ    = (float*)smraw;
    float*  sBias = sQ + QT*KD;
    float*  sInv  = sBias + NKEY;
    __half* sS    = (__half*)(smraw + (QT*KD + NKEY + 32)*4);
    __half* sV    = sS + 32*SPH;
    const int tid = threadIdx.x;
    const int q0 = qt * QT;

    for (int i = tid; i < QT*KD; i += 256) {
        int q = i / KD, t = i % KD;
        sQ[i] = __half2float(g_qh[((size_t)(b*NQ) + q0 + q) * (NH*KD) + h*KD + t]);
    }
    for (int i = tid; i < NKEY; i += 256) sBias[i] = attn_bias[h*NKEY + i];
    for (int i = tid; i < 4*SPH; i += 256) sS[28*SPH + i] = __ushort_as_half(0);
    __syncthreads();

    // phase 1: S = 0.25 * q.k + bias -> f16 (K stays f32 for score precision)
    for (int j = tid; j < NKEY; j += 256) {
        float kr[KD];
        const float4* kp = reinterpret_cast<const float4*>(
            g_k + ((size_t)(b*NKEY) + j) * (NH*KD) + h*KD);
#pragma unroll
        for (int t = 0; t < 4; t++) {
            float4 v = kp[t];
            kr[t*4+0] = v.x; kr[t*4+1] = v.y; kr[t*4+2] = v.z; kr[t*4+3] = v.w;
        }
        const int jx = j % RES, jy = j / RES;
#pragma unroll 2
        for (int q = 0; q < QT; q++) {
            const int qg = q0 + q;
            const int qx = 2*(qg % RES2), qy = 2*(qg / RES2);
            float s = 0.f;
#pragma unroll
            for (int t = 0; t < KD; t++) s += sQ[q*KD + t] * kr[t];
            const int dxa = qx > jx ? qx - jx : jx - qx;
            const int dya = qy > jy ? qy - jy : jy - qy;
            sS[q*SPH + j] = __float2half(s * 0.25f + sBias[dxa*RES + dya]);
        }
    }
    __syncthreads();

    // phase 2: softmax
    const int warp = tid >> 5, lane = tid & 31;
    for (int r = warp; r < QT; r += 8) {
        float m = -1e30f;
        for (int j = lane; j < NKEY; j += 32) m = fmaxf(m, __half2float(sS[r*SPH + j]));
#pragma unroll
        for (int o = 16; o > 0; o >>= 1) m = fmaxf(m, __shfl_xor_sync(0xffffffffu, m, o));
        float sum = 0.f;
        for (int j = lane; j < NKEY; j += 32) {
            float e = __expf(__half2float(sS[r*SPH + j]) - m);
            __half he = __float2half(e);
            sS[r*SPH + j] = he;
            sum += __half2float(he);
        }
#pragma unroll
        for (int o = 16; o > 0; o >>= 1) sum += __shfl_xor_sync(0xffffffffu, sum, o);
        if (lane == 0) sInv[r] = 1.f / sum;
    }
    __syncthreads();

    // phase 3: O = P @ V via mma.m16n8k16 + ldmatrix; V staged via cp.async (f16 src)
    const int grp = lane >> 2, t4 = lane & 3;
    const int l16 = lane & 15, lhi8 = (lane >> 4) * 8;
    float c[2][4] = {{0.f,0.f,0.f,0.f},{0.f,0.f,0.f,0.f}};

    for (int kt = 0; kt < NKEY; kt += VTILE) {
        // stage V tile: VTILE rows x 64 halves; 8 x 16B chunks per row
        for (int i = tid; i < VTILE*8; i += 256) {
            int j = i >> 3, c8 = i & 7;
            CP_ASYNC16(smaddr(&sV[j*VP + c8*8]),
                       &g_vh[((size_t)(b*NKEY) + kt + j) * DH + h*DV + c8*8]);
        }
        CP_COMMIT();
        CP_WAIT(0);
        __syncthreads();

#pragma unroll
        for (int ks = 0; ks < VTILE; ks += 16) {
            const int kg = kt + ks;
            uint32_t b0, b1;
            ldsm_x2t(b0, b1, smaddr(&sV[(ks + l16) * VP + warp*8]));
#pragma unroll
            for (int mt = 0; mt < 2; mt++) {
                uint32_t a0, a1, a2, a3;
                ldsm_x4(a0, a1, a2, a3,
                        smaddr(&sS[(mt*16 + l16) * SPH + kg + lhi8]));
                asm volatile(
                    "mma.sync.aligned.m16n8k16.row.col.f32.f16.f16.f32 "
                    "{%0,%1,%2,%3}, {%4,%5,%6,%7}, {%8,%9}, {%0,%1,%2,%3};\n"
                    : "+f"(c[mt][0]), "+f"(c[mt][1]), "+f"(c[mt][2]), "+f"(c[mt][3])
                    : "r"(a0), "r"(a1), "r"(a2), "r"(a3), "r"(b0), "r"(b1));
            }
        }
        __syncthreads();
    }

    // epilogue -> f16 (+ v_local)
    {
        const int ocol = warp*8 + 2*t4;
#pragma unroll
        for (int mt = 0; mt < 2; mt++) {
            int r0 = mt*16 + grp;
            size_t o0 = ((size_t)(b*NQ) + q0 + r0) * DH + h*DV + ocol;
            float inv0 = sInv[r0];
            g_aoh[o0]     = __float2half(c[mt][0] * inv0 + g_vloc[o0]);
            g_aoh[o0 + 1] = __float2half(c[mt][1] * inv0 + g_vloc[o0 + 1]);
            int r1 = mt*16 + 8 + grp;
            if (r1 < QT) {
                size_t o1 = ((size_t)(b*NQ) + q0 + r1) * DH + h*DV + ocol;
                float inv1 = sInv[r1];
                g_aoh[o1]     = __float2half(c[mt][2] * inv1 + g_vloc[o1]);
                g_aoh[o1 + 1] = __float2half(c[mt][3] * inv1 + g_vloc[o1 + 1]);
            }
        }
    }
}

// ---------------- launch ----------------
extern "C" void kernel_launch(void* const* d_in, const int* in_sizes, int n_in,
                              void* d_out, int out_size) {
    const float* x         = (const float*)d_in[0];
    const float* q_local_w = (const float*)d_in[1];
    const float* q_local_b = (const float*)d_in[2];
    const float* q_proj_w  = (const float*)d_in[3];
    const float* q_proj_b  = (const float*)d_in[4];
    const float* q_bn_s    = (const float*)d_in[5];
    const float* q_bn_b    = (const float*)d_in[6];
    const float* k_w       = (const float*)d_in[7];
    const float* k_b       = (const float*)d_in[8];
    const float* k_bn_s    = (const float*)d_in[9];
    const float* k_bn_b    = (const float*)d_in[10];
    const float* v_w       = (const float*)d_in[11];
    const float* v_b       = (const float*)d_in[12];
    const float* v_bn_s    = (const float*)d_in[13];
    const float* v_bn_b    = (const float*)d_in[14];
    const float* vloc_w    = (const float*)d_in[15];
    const float* vloc_b    = (const float*)d_in[16];
    const float* vloc_bn_s = (const float*)d_in[17];
    const float* vloc_bn_b = (const float*)d_in[18];
    const float* proj_w    = (const float*)d_in[19];
    const float* proj_b    = (const float*)d_in[20];
    const float* proj_bn_s = (const float*)d_in[21];
    const float* proj_bn_b = (const float*)d_in[22];
    const float* attn_bias = (const float*)d_in[23];
    float* out = (float*)d_out;

    __half *p_xh, *p_qdsh, *p_aoh, *p_wqh, *p_wkh, *p_wvh, *p_wph, *p_qh, *p_vh;
    float  *p_k;
    cudaGetSymbolAddress((void**)&p_xh,   g_xh);
    cudaGetSymbolAddress((void**)&p_qdsh, g_qdsh);
    cudaGetSymbolAddress((void**)&p_aoh,  g_aoh);
    cudaGetSymbolAddress((void**)&p_wqh,  g_wqh);
    cudaGetSymbolAddress((void**)&p_wkh,  g_wkh);
    cudaGetSymbolAddress((void**)&p_wvh,  g_wvh);
    cudaGetSymbolAddress((void**)&p_wph,  g_wph);
    cudaGetSymbolAddress((void**)&p_qh,   g_qh);
    cudaGetSymbolAddress((void**)&p_vh,   g_vh);
    cudaGetSymbolAddress((void**)&p_k,    g_k);

    cudaFuncSetAttribute(gemm_f16_kernel<float>,  cudaFuncAttributeMaxDynamicSharedMemorySize, GEMM_SMEM);
    cudaFuncSetAttribute(gemm_f16_kernel<__half>, cudaFuncAttributeMaxDynamicSharedMemorySize, GEMM_SMEM);
    cudaFuncSetAttribute(attn_kernel,             cudaFuncAttributeMaxDynamicSharedMemorySize, ATTN_SMEM);

    // prep: f16 conversions
    {
        int n4 = MK * CIN / 4;
        cvt_f16_kernel<<<(n4 + 255)/256, 256>>>(x, p_xh, n4);
        cvt_f16_kernel<<<(CIN*128/4 + 255)/256, 256>>>(q_proj_w, p_wqh, CIN*128/4);
        cvt_f16_kernel<<<(CIN*128/4 + 255)/256, 256>>>(k_w,      p_wkh, CIN*128/4);
        cvt_f16_kernel<<<(CIN*DH/4  + 255)/256, 256>>>(v_w,      p_wvh, CIN*DH/4);
        cvt_f16_kernel<<<(DH*COUT/4 + 255)/256, 256>>>(proj_w,   p_wph, DH*COUT/4);
    }
    // 1. q local conv -> g_qdsh (f16)
    {
        int total = BATCH * NQ * CIN;
        conv_q_kernel<<<(total + 255)/256, 256>>>(x, q_local_w, q_local_b);
    }
    // 2. q projection -> f16
    gemm_f16_kernel<__half><<<dim3(1, MQ/GBM), 256, GEMM_SMEM>>>(p_qdsh, p_wqh, q_proj_b, q_bn_s, q_bn_b, p_qh, MQ, 128, CIN);
    // 3. k -> f32
    gemm_f16_kernel<float><<<dim3(1, MK/GBM), 256, GEMM_SMEM>>>(p_xh, p_wkh, k_b, k_bn_s, k_bn_b, p_k, MK, 128, CIN);
    // 4. v -> f16
    gemm_f16_kernel<__half><<<dim3(DH/GBN, MK/GBM), 256, GEMM_SMEM>>>(p_xh, p_wvh, v_b, v_bn_s, v_bn_b, p_vh, MK, DH, CIN);
    // 5. v_local conv (reads f16 v)
    {
        int total = BATCH * NQ * DH;
        conv_vloc_kernel<<<(total + 255)/256, 256>>>(vloc_w, vloc_b, vloc_bn_s, vloc_bn_b);
    }
    // 6. attention (+v_local) -> g_aoh (f16)
    attn_kernel<<<dim3(NQ/QT, NH, BATCH), 256, ATTN_SMEM>>>(attn_bias);
    // 7. projection -> f32 out
    gemm_f16_kernel<float><<<dim3(COUT/GBN, MQ/GBM), 256, GEMM_SMEM>>>(p_aoh, p_wph, proj_b, proj_bn_s, proj_bn_b, out, MQ, COUT, DH);
}